// round 14
// baseline (speedup 1.0000x reference)
#include <cuda_runtime.h>
#include <cuda_bf16.h>
#include <math.h>
#include <stdint.h>

#define C_DIM 256
#define CH_DIM 128
#define NSEQ 4096
#define BS 2
#define DH 64
#define NH 4
#define EPS 1e-5f
#define C1F 0.1803368801111204f   // 0.125 * log2(e)

// weight pack offsets (elements)
#define WOFF_Q 0
#define WOFF_K 65536
#define WOFF_V 131072
#define WOFF_1 196608
#define WOFF_2 229376
#define WOFF_3 245760
#define WTOT   278528

// ---------------- scratch ----------------
__device__ __align__(128) __nv_bfloat16 g_featbf[BS * C_DIM * NSEQ];
__device__ __align__(128) __nv_bfloat16 g_Wbf[WTOT];
__device__ __align__(128) __nv_bfloat16 g_Qt[BS * C_DIM * NSEQ];   // [bh][n][64] (pre-scaled by C1)
__device__ __align__(128) __nv_bfloat16 g_Kt[BS * C_DIM * NSEQ];   // [bh][n][64]
__device__ __align__(128) __nv_bfloat16 g_Vc[BS * C_DIM * NSEQ];   // [b][256][4096]
__device__ __align__(128) __nv_bfloat16 g_xdiff[BS * C_DIM * NSEQ];
__device__ float g_msg2[BS * C_DIM * NSEQ];
__device__ float g_chansum[BS * C_DIM];

// ---------------- PTX helpers ----------------
__device__ __forceinline__ uint32_t s2u(const void* p) {
    uint32_t a;
    asm("{ .reg .u64 t; cvta.to.shared.u64 t, %1; cvt.u32.u64 %0, t; }" : "=r"(a) : "l"(p));
    return a;
}
__device__ __forceinline__ uint32_t sw128(uint32_t x) { return x ^ ((x >> 3) & 0x70); }

__device__ __forceinline__ void cpa16(uint32_t s, const void* g) {
    asm volatile("cp.async.cg.shared.global [%0], [%1], 16;" :: "r"(s), "l"(g));
}
__device__ __forceinline__ void cpa_commit() { asm volatile("cp.async.commit_group;" ::: "memory"); }
__device__ __forceinline__ void cpa_wait1()  { asm volatile("cp.async.wait_group 1;" ::: "memory"); }
__device__ __forceinline__ void cpa_wait0()  { asm volatile("cp.async.wait_group 0;" ::: "memory"); }

__device__ __forceinline__ void ldsm4(uint32_t r[4], uint32_t addr) {
    asm volatile("ldmatrix.sync.aligned.m8n8.x4.shared.b16 {%0,%1,%2,%3}, [%4];"
                 : "=r"(r[0]), "=r"(r[1]), "=r"(r[2]), "=r"(r[3]) : "r"(addr));
}
__device__ __forceinline__ void ldsm4t(uint32_t r[4], uint32_t addr) {
    asm volatile("ldmatrix.sync.aligned.m8n8.x4.trans.shared.b16 {%0,%1,%2,%3}, [%4];"
                 : "=r"(r[0]), "=r"(r[1]), "=r"(r[2]), "=r"(r[3]) : "r"(addr));
}

__device__ __forceinline__ void mma16816(float d[4], const uint32_t a[4], uint32_t b0, uint32_t b1) {
    asm volatile(
        "mma.sync.aligned.m16n8k16.row.col.f32.bf16.bf16.f32 "
        "{%0,%1,%2,%3}, {%4,%5,%6,%7}, {%8,%9}, {%0,%1,%2,%3};"
        : "+f"(d[0]), "+f"(d[1]), "+f"(d[2]), "+f"(d[3])
        : "r"(a[0]), "r"(a[1]), "r"(a[2]), "r"(a[3]), "r"(b0), "r"(b1));
}

__device__ __forceinline__ float ex2f(float x) {
    float y; asm("ex2.approx.ftz.f32 %0, %1;" : "=f"(y) : "f"(x)); return y;
}
__device__ __forceinline__ uint32_t packbf2(float lo, float hi) {
    __nv_bfloat162 h = __floats2bfloat162_rn(lo, hi);
    return *(uint32_t*)&h;
}

__device__ __forceinline__ uint32_t addrA(uint32_t base, int row0, int seg0, int lane) {
    int g = lane >> 3, i = lane & 7;
    int r = row0 + i + ((g & 1) << 3);
    int s = seg0 + (g >> 1);
    return base + sw128((uint32_t)(r * 128 + s * 16));
}
__device__ __forceinline__ uint32_t addrB(uint32_t base, int row0, int seg0, int lane) {
    int g = lane >> 3, i = lane & 7;
    int r = row0 + i + ((g >> 1) << 3);
    int s = seg0 + (g & 1);
    return base + sw128((uint32_t)(r * 128 + s * 16));
}

// ---------------- converts (merged, + chansum zero) ----------------
__global__ void convert_all(const float* __restrict__ feat,
                            const float* __restrict__ Wq, const float* __restrict__ Wk,
                            const float* __restrict__ Wv, const float* __restrict__ W1,
                            const float* __restrict__ W2, const float* __restrict__ W3) {
    int i = blockIdx.x * blockDim.x + threadIdx.x;
    if (i < BS * C_DIM) g_chansum[i] = 0.0f;
    const int tot2 = BS * C_DIM * NSEQ / 2;
    if (i < tot2) {
        float2 v = ((const float2*)feat)[i];
        ((__nv_bfloat162*)g_featbf)[i] = __floats2bfloat162_rn(v.x, v.y);
    }
    if (i < WTOT) {
        float v;
        if      (i < WOFF_K) v = Wq[i - WOFF_Q];
        else if (i < WOFF_V) v = Wk[i - WOFF_K];
        else if (i < WOFF_1) v = Wv[i - WOFF_V];
        else if (i < WOFF_2) v = W1[i - WOFF_1];
        else if (i < WOFF_3) v = W2[i - WOFF_2];
        else                 v = W3[i - WOFF_3];
        g_Wbf[i] = __float2bfloat16(v);
    }
}

// ---------------- qkv fused: single-barrier pipelines in both branches ----------------
__global__ __launch_bounds__(256, 2) void qkv_kernel(
    const __nv_bfloat16* __restrict__ Wqb, const __nv_bfloat16* __restrict__ Wkb,
    const __nv_bfloat16* __restrict__ Wvb, const __nv_bfloat16* __restrict__ X,
    const float* __restrict__ bq, const float* __restrict__ bk, const float* __restrict__ bv,
    __nv_bfloat16* __restrict__ outQ, __nv_bfloat16* __restrict__ outK,
    __nv_bfloat16* __restrict__ outV)
{
    extern __shared__ __align__(128) __nv_bfloat16 dyns[];
    const int tid = threadIdx.x, lane = tid & 31, w = tid >> 5;
    const int b = blockIdx.z;
    const __nv_bfloat16* Xb = X + (size_t)b * C_DIM * NSEQ;
    const uint32_t base = s2u(dyns);

    if (blockIdx.y < 4) {
        const int s0 = blockIdx.x * 128, ch0 = blockIdx.y * 64;

        auto load_stage = [&](int st, int k0) {
            const uint32_t Xa = base + st * 16384u;
            const uint32_t Qa = base + 32768u + st * 8192u;
            const uint32_t Ka = base + 49152u + st * 8192u;
            #pragma unroll
            for (int i = 0; i < 4; i++) {
                int e = tid + i * 256; int r = e >> 4, c = e & 15;
                int h = c >> 3, sg = c & 7;
                cpa16(Xa + h * 8192u + sw128((uint32_t)(r * 128 + sg * 16)),
                      Xb + (size_t)(k0 + r) * NSEQ + s0 + h * 64 + sg * 8);
            }
            #pragma unroll
            for (int i = 0; i < 2; i++) {
                int e = tid + i * 256; int r = e >> 3, sg = e & 7;
                cpa16(Qa + sw128((uint32_t)(r * 128 + sg * 16)), Wqb + (size_t)(ch0 + r) * 256 + k0 + sg * 8);
                cpa16(Ka + sw128((uint32_t)(r * 128 + sg * 16)), Wkb + (size_t)(ch0 + r) * 256 + k0 + sg * 8);
            }
        };

        load_stage(0, 0);
        cpa_commit();

        float qacc[8][4], kacc[8][4];
        #pragma unroll
        for (int j = 0; j < 8; j++)
            #pragma unroll
            for (int x = 0; x < 4; x++) { qacc[j][x] = 0.0f; kacc[j][x] = 0.0f; }

        for (int kt = 0; kt < 4; kt++) {
            cpa_wait0();
            __syncthreads();
            if (kt + 1 < 4) {
                load_stage((kt + 1) & 1, (kt + 1) * 64);
                cpa_commit();
            }

            const int st = kt & 1;
            const uint32_t Xh = base + st * 16384u + (w >> 2) * 8192u;
            const uint32_t Qa = base + 32768u + st * 8192u;
            const uint32_t Ka = base + 49152u + st * 8192u;

            uint32_t a[4][4];
            #pragma unroll
            for (int kk = 0; kk < 4; kk++)
                ldsm4t(a[kk], addrB(Xh, kk * 16, (w & 3) * 2, lane));

            #pragma unroll
            for (int j2 = 0; j2 < 4; j2++) {
                #pragma unroll
                for (int kk = 0; kk < 4; kk++) {
                    uint32_t bf[4];
                    ldsm4(bf, addrB(Qa, j2 * 16, kk * 2, lane));
                    mma16816(qacc[2 * j2],     a[kk], bf[0], bf[1]);
                    mma16816(qacc[2 * j2 + 1], a[kk], bf[2], bf[3]);
                }
                #pragma unroll
                for (int kk = 0; kk < 4; kk++) {
                    uint32_t bf[4];
                    ldsm4(bf, addrB(Ka, j2 * 16, kk * 2, lane));
                    mma16816(kacc[2 * j2],     a[kk], bf[0], bf[1]);
                    mma16816(kacc[2 * j2 + 1], a[kk], bf[2], bf[3]);
                }
            }
        }

        const int qA = s0 + w * 16 + (lane >> 2);
        const int qB = qA + 8;
        const size_t obo = ((size_t)(b * NH + blockIdx.y) * NSEQ) * 64;
        __nv_bfloat16* obQ = outQ + obo;
        __nv_bfloat16* obK = outK + obo;
        #pragma unroll
        for (int j = 0; j < 8; j++) {
            const int chl = j * 8 + (lane & 3) * 2;
            float2 bbq = *(const float2*)&bq[ch0 + chl];
            float2 bbk = *(const float2*)&bk[ch0 + chl];
            *(uint32_t*)&obQ[(size_t)qA * 64 + chl] = packbf2((qacc[j][0] + bbq.x) * C1F, (qacc[j][1] + bbq.y) * C1F);
            *(uint32_t*)&obQ[(size_t)qB * 64 + chl] = packbf2((qacc[j][2] + bbq.x) * C1F, (qacc[j][3] + bbq.y) * C1F);
            *(uint32_t*)&obK[(size_t)qA * 64 + chl] = packbf2(kacc[j][0] + bbk.x, kacc[j][1] + bbk.y);
            *(uint32_t*)&obK[(size_t)qB * 64 + chl] = packbf2(kacc[j][2] + bbk.x, kacc[j][3] + bbk.y);
        }
    } else {
        const int n0 = blockIdx.x * 128, m0 = (blockIdx.y - 4) * 64;
        const int mw = w & 3, nw = w >> 2;

        auto load_stage = [&](int st, int k0) {
            const uint32_t Aa = base + st * 24576u;
            const uint32_t Ba = Aa + 8192u;
            #pragma unroll
            for (int i = 0; i < 2; i++) {
                int e = tid + i * 256; int r = e >> 3, sg = e & 7;
                cpa16(Aa + sw128((uint32_t)(r * 128 + sg * 16)), Wvb + (size_t)(m0 + r) * 256 + k0 + sg * 8);
            }
            #pragma unroll
            for (int i = 0; i < 4; i++) {
                int e = tid + i * 256; int r = e >> 4, c = e & 15;
                int h = c >> 3, sg = c & 7;
                cpa16(Ba + h * 8192u + sw128((uint32_t)(r * 128 + sg * 16)),
                      Xb + (size_t)(k0 + r) * NSEQ + n0 + h * 64 + sg * 8);
            }
        };

        load_stage(0, 0);
        cpa_commit();

        float sacc[8][4];
        #pragma unroll
        for (int j = 0; j < 8; j++)
            #pragma unroll
            for (int x = 0; x < 4; x++) sacc[j][x] = 0.0f;

        for (int kt = 0; kt < 4; kt++) {
            cpa_wait0();
            __syncthreads();
            if (kt + 1 < 4) {
                load_stage((kt + 1) & 1, (kt + 1) * 64);
                cpa_commit();
            }

            const uint32_t Aa = base + (kt & 1) * 24576u;
            const uint32_t Bh = Aa + 8192u + nw * 8192u;

            uint32_t a[4][4];
            #pragma unroll
            for (int kk = 0; kk < 4; kk++)
                ldsm4(a[kk], addrA(Aa, mw * 16, kk * 2, lane));

            #pragma unroll
            for (int j2 = 0; j2 < 4; j2++) {
                #pragma unroll
                for (int kk = 0; kk < 4; kk++) {
                    uint32_t bf[4];
                    ldsm4t(bf, addrA(Bh, kk * 16, j2 * 2, lane));
                    mma16816(sacc[2 * j2],     a[kk], bf[0], bf[1]);
                    mma16816(sacc[2 * j2 + 1], a[kk], bf[2], bf[3]);
                }
            }
        }

        const int mA = m0 + mw * 16 + (lane >> 2);
        const int mB = mA + 8;
        const float biasA = bv[mA], biasB = bv[mB];
        __nv_bfloat16* ob = outV + (size_t)b * C_DIM * NSEQ;
        #pragma unroll
        for (int j = 0; j < 8; j++) {
            const int nl = n0 + nw * 64 + j * 8 + (lane & 3) * 2;
            *(uint32_t*)&ob[(size_t)mA * NSEQ + nl] = packbf2(sacc[j][0] + biasA, sacc[j][1] + biasA);
            *(uint32_t*)&ob[(size_t)mB * NSEQ + nl] = packbf2(sacc[j][2] + biasB, sacc[j][3] + biasB);
        }
    }
}

// ---------------- flash attention (R13 best: single barrier per iteration) ----------------
__global__ __launch_bounds__(256, 2) void flash_mma(
    const __nv_bfloat16* __restrict__ Qt,
    const __nv_bfloat16* __restrict__ Kt,
    const __nv_bfloat16* __restrict__ Vc,
    const float* __restrict__ feat,
    __nv_bfloat16* __restrict__ xdiff)
{
    extern __shared__ __align__(128) __nv_bfloat16 fsm[];
    const uint32_t base = s2u(fsm);

    const int tid = threadIdx.x;
    const int lane = tid & 31;
    const int w = tid >> 5;
    const int bh = blockIdx.y;
    const int q0 = blockIdx.x * 128;

    const uint32_t QSa = base;

    const __nv_bfloat16* Qg = Qt + (size_t)bh * NSEQ * 64;
    const __nv_bfloat16* Kg = Kt + (size_t)bh * NSEQ * 64;
    const __nv_bfloat16* Vg = Vc + (size_t)bh * 64 * NSEQ;

    auto load_kv = [&](int st, int k0) {
        const uint32_t KS = base + 16384u + (uint32_t)st * 32768u;
        const uint32_t VS = KS + 16384u;
        #pragma unroll
        for (int i = 0; i < 4; i++) {
            int e = tid + i * 256;
            int row = e >> 3, sg = e & 7;
            cpa16(KS + sw128((uint32_t)(row * 128 + sg * 16)), Kg + (size_t)(k0 + row) * 64 + sg * 8);
        }
        #pragma unroll
        for (int i = 0; i < 4; i++) {
            int e = tid + i * 256;
            int c = e >> 4, rem = e & 15;
            int p = rem >> 3, sg = rem & 7;
            cpa16(VS + p * 8192u + sw128((uint32_t)(c * 128 + sg * 16)),
                  Vg + (size_t)c * NSEQ + k0 + p * 64 + sg * 8);
        }
    };

    #pragma unroll
    for (int i = 0; i < 4; i++) {
        int e = tid + i * 256;
        int row = e >> 3, sg = e & 7;
        cpa16(QSa + sw128((uint32_t)(row * 128 + sg * 16)), Qg + (size_t)(q0 + row) * 64 + sg * 8);
    }
    load_kv(0, 0);
    cpa_commit();

    float l_lo = 0.0f, l_hi = 0.0f;
    float oacc[8][4];
    #pragma unroll
    for (int j = 0; j < 8; j++)
        #pragma unroll
        for (int x = 0; x < 4; x++) oacc[j][x] = 0.0f;
    uint32_t qa[4][4];

    for (int t = 0; t < 32; t++) {
        const int cur = t & 1;
        cpa_wait0();
        __syncthreads();

        if (t + 1 < 32) {
            load_kv(1 - cur, (t + 1) * 128);
            cpa_commit();
        }

        if (t == 0) {
            #pragma unroll
            for (int kk = 0; kk < 4; kk++)
                ldsm4(qa[kk], addrA(QSa, w * 16, kk * 2, lane));
        }

        const uint32_t KS = base + 16384u + (uint32_t)cur * 32768u;
        const uint32_t VS = KS + 16384u;

        #pragma unroll
        for (int j2 = 0; j2 < 8; j2++) {
            float s0a[4] = {0.0f, 0.0f, 0.0f, 0.0f};
            float s1a[4] = {0.0f, 0.0f, 0.0f, 0.0f};
            #pragma unroll
            for (int kk = 0; kk < 4; kk++) {
                uint32_t bq[4];
                ldsm4(bq, addrB(KS, j2 * 16, kk * 2, lane));
                mma16816(s0a, qa[kk], bq[0], bq[1]);
                mma16816(s1a, qa[kk], bq[2], bq[3]);
            }

            uint32_t a[4];
            {
                float p0 = ex2f(s0a[0]);
                float p1 = ex2f(s0a[1]);
                float p2 = ex2f(s0a[2]);
                float p3 = ex2f(s0a[3]);
                l_lo += p0 + p1; l_hi += p2 + p3;
                a[0] = packbf2(p0, p1);
                a[1] = packbf2(p2, p3);
                float p4 = ex2f(s1a[0]);
                float p5 = ex2f(s1a[1]);
                float p6 = ex2f(s1a[2]);
                float p7 = ex2f(s1a[3]);
                l_lo += p4 + p5; l_hi += p6 + p7;
                a[2] = packbf2(p4, p5);
                a[3] = packbf2(p6, p7);
            }

            const uint32_t Vp = VS + (uint32_t)(j2 >> 2) * 8192u;
            const int seg0 = (j2 & 3) * 2;
            #pragma unroll
            for (int cp = 0; cp < 4; cp++) {
                uint32_t bv4[4];
                ldsm4(bv4, addrB(Vp, cp * 16, seg0, lane));
                mma16816(oacc[2 * cp],     a, bv4[0], bv4[1]);
                mma16816(oacc[2 * cp + 1], a, bv4[2], bv4[3]);
            }
        }
    }

    l_lo += __shfl_xor_sync(0xffffffffu, l_lo, 1);
    l_lo += __shfl_xor_sync(0xffffffffu, l_lo, 2);
    l_hi += __shfl_xor_sync(0xffffffffu, l_hi, 1);
    l_hi += __shfl_xor_sync(0xffffffffu, l_hi, 2);
    const float inv_lo = 1.0f / l_lo;
    const float inv_hi = 1.0f / l_hi;

    __nv_bfloat16* Ms = fsm + 8192;
    const int qrl = w * 16 + (lane >> 2);
    #pragma unroll
    for (int ct = 0; ct < 8; ct++) {
        const int ch = ct * 8 + (lane & 3) * 2;
        Ms[ch * 136 + qrl]           = __float2bfloat16(oacc[ct][0] * inv_lo);
        Ms[(ch + 1) * 136 + qrl]     = __float2bfloat16(oacc[ct][1] * inv_lo);
        Ms[ch * 136 + qrl + 8]       = __float2bfloat16(oacc[ct][2] * inv_hi);
        Ms[(ch + 1) * 136 + qrl + 8] = __float2bfloat16(oacc[ct][3] * inv_hi);
    }
    __syncthreads();

    const float* fg = feat + (size_t)bh * 64 * NSEQ;
    __nv_bfloat16* xd = xdiff + (size_t)bh * 64 * NSEQ;
    #pragma unroll
    for (int i = 0; i < 16; i++) {
        int idx = tid + i * 256;
        int ch = idx >> 6, qp = (idx & 63) * 2;
        float2 f = *(const float2*)&fg[(size_t)ch * NSEQ + q0 + qp];
        float m0v = __bfloat162float(Ms[ch * 136 + qp]);
        float m1v = __bfloat162float(Ms[ch * 136 + qp + 1]);
        *(uint32_t*)&xd[(size_t)ch * NSEQ + q0 + qp] = packbf2(f.x - m0v, f.y - m1v);
    }
}

// ---------------- fused MLP (unchanged) ----------------
__device__ __forceinline__ void mlp_load_W(uint32_t dst, const __nv_bfloat16* W, int M, int K, int tid) {
    const int chunks = K >> 6;
    const int per_chunk = M * 8;
    const int total = chunks * per_chunk;
    for (int u = tid; u < total; u += 256) {
        int kc = u / per_chunk;
        int rem = u - kc * per_chunk;
        int m = rem >> 3, sg = rem & 7;
        cpa16(dst + (uint32_t)(kc * M * 128) + sw128((uint32_t)(m * 128 + sg * 16)),
              W + (size_t)m * K + kc * 64 + sg * 8);
    }
}

__global__ __launch_bounds__(256) void fused_mlp(
    const __nv_bfloat16* __restrict__ Wb,
    const __nv_bfloat16* __restrict__ xdiff,
    const float* __restrict__ b1, const float* __restrict__ g1, const float* __restrict__ be1,
    const float* __restrict__ m1, const float* __restrict__ v1,
    const float* __restrict__ b2, const float* __restrict__ g2, const float* __restrict__ be2,
    const float* __restrict__ m2, const float* __restrict__ v2,
    const float* __restrict__ b3,
    float* __restrict__ msg2)
{
    extern __shared__ __align__(128) __nv_bfloat16 dyns[];
    const int tid = threadIdx.x, lane = tid & 31, w = tid >> 5;
    const int s0 = blockIdx.x * 64, b = blockIdx.y;
    const uint32_t base = s2u(dyns);
    const uint32_t XD = base, H1 = base + 32768u, H2 = base + 49152u;
    const uint32_t WB0 = base + 65536u, WB1 = base + 131072u;

    const __nv_bfloat16* xd_g = xdiff + (size_t)b * C_DIM * NSEQ;

    for (int u = tid; u < 2048; u += 256) {
        int r = u >> 3, sg = u & 7;
        cpa16(XD + sw128((uint32_t)(r * 128 + sg * 16)), xd_g + (size_t)r * NSEQ + s0 + sg * 8);
    }
    mlp_load_W(WB0, Wb + WOFF_1, 128, 256, tid);
    cpa_commit();
    mlp_load_W(WB1, Wb + WOFF_2, 128, 128, tid);
    cpa_commit();

    cpa_wait1();
    __syncthreads();

    {
        float sacc[8][4];
        #pragma unroll
        for (int j = 0; j < 8; j++)
            #pragma unroll
            for (int x = 0; x < 4; x++) sacc[j][x] = 0.0f;

        for (int kc = 0; kc < 4; kc++) {
            const uint32_t Ac = WB0 + kc * 16384u;
            const uint32_t Bc = XD + kc * 8192u;
            uint32_t a[4][4];
            #pragma unroll
            for (int kk = 0; kk < 4; kk++)
                ldsm4(a[kk], addrA(Ac, w * 16, kk * 2, lane));
            #pragma unroll
            for (int j2 = 0; j2 < 4; j2++) {
                #pragma unroll
                for (int kk = 0; kk < 4; kk++) {
                    uint32_t bf[4];
                    ldsm4t(bf, addrA(Bc, kk * 16, j2 * 2, lane));
                    mma16816(sacc[2 * j2],     a[kk], bf[0], bf[1]);
                    mma16816(sacc[2 * j2 + 1], a[kk], bf[2], bf[3]);
                }
            }
        }

        const int mA = w * 16 + (lane >> 2);
        const int mB = mA + 8;
        float scA = g1[mA] * rsqrtf(v1[mA] + EPS), shA = be1[mA] - m1[mA] * scA;
        float scB = g1[mB] * rsqrtf(v1[mB] + EPS), shB = be1[mB] - m1[mB] * scB;
        const float bA = b1[mA], bB = b1[mB];
        #pragma unroll
        for (int j = 0; j < 8; j++) {
            const int nl = j * 8 + (lane & 3) * 2;
            float v0 = fmaxf((sacc[j][0] + bA) * scA + shA, 0.0f);
            float v1x = fmaxf((sacc[j][1] + bA) * scA + shA, 0.0f);
            float v2x = fmaxf((sacc[j][2] + bB) * scB + shB, 0.0f);
            float v3 = fmaxf((sacc[j][3] + bB) * scB + shB, 0.0f);
            *(uint32_t*)((char*)dyns + (H1 - base) + sw128((uint32_t)(mA * 128 + nl * 2))) = packbf2(v0, v1x);
            *(uint32_t*)((char*)dyns + (H1 - base) + sw128((uint32_t)(mB * 128 + nl * 2))) = packbf2(v2x, v3);
        }
    }
    __syncthreads();

    mlp_load_W(WB0, Wb + WOFF_3, 256, 128, tid);
    cpa_commit();

    cpa_wait1();
    __syncthreads();

    {
        float sacc[8][4];
        #pragma unroll
        for (int j = 0; j < 8; j++)
            #pragma unroll
            for (int x = 0; x < 4; x++) sacc[j][x] = 0.0f;

        for (int kc = 0; kc < 2; kc++) {
            const uint32_t Ac = WB1 + kc * 16384u;
            const uint32_t Bc = H1 + kc * 8192u;
            uint32_t a[4][4];
            #pragma unroll
            for (int kk = 0; kk < 4; kk++)
                ldsm4(a[kk], addrA(Ac, w * 16, kk * 2, lane));
            #pragma unroll
            for (int j2 = 0; j2 < 4; j2++) {
                #pragma unroll
                for (int kk = 0; kk < 4; kk++) {
                    uint32_t bf[4];
                    ldsm4t(bf, addrA(Bc, kk * 16, j2 * 2, lane));
                    mma16816(sacc[2 * j2],     a[kk], bf[0], bf[1]);
                    mma16816(sacc[2 * j2 + 1], a[kk], bf[2], bf[3]);
                }
            }
        }

        const int mA = w * 16 + (lane >> 2);
        const int mB = mA + 8;
        float scA = g2[mA] * rsqrtf(v2[mA] + EPS), shA = be2[mA] - m2[mA] * scA;
        float scB = g2[mB] * rsqrtf(v2[mB] + EPS), shB = be2[mB] - m2[mB] * scB;
        const float bA = b2[mA], bB = b2[mB];
        #pragma unroll
        for (int j = 0; j < 8; j++) {
            const int nl = j * 8 + (lane & 3) * 2;
            float v0 = fmaxf((sacc[j][0] + bA) * scA + shA, 0.0f);
            float v1x = fmaxf((sacc[j][1] + bA) * scA + shA, 0.0f);
            float v2x = fmaxf((sacc[j][2] + bB) * scB + shB, 0.0f);
            float v3 = fmaxf((sacc[j][3] + bB) * scB + shB, 0.0f);
            *(uint32_t*)((char*)dyns + (H2 - base) + sw128((uint32_t)(mA * 128 + nl * 2))) = packbf2(v0, v1x);
            *(uint32_t*)((char*)dyns + (H2 - base) + sw128((uint32_t)(mB * 128 + nl * 2))) = packbf2(v2x, v3);
        }
    }
    __syncthreads();

    cpa_wait0();
    __syncthreads();

    float* of = msg2 + (size_t)b * C_DIM * NSEQ;
    #pragma unroll
    for (int ms = 0; ms < 2; ms++) {
        float sacc[8][4];
        #pragma unroll
        for (int j = 0; j < 8; j++)
            #pragma unroll
            for (int x = 0; x < 4; x++) sacc[j][x] = 0.0f;

        const int mbase = ms * 128 + w * 16;
        for (int kc = 0; kc < 2; kc++) {
            const uint32_t Ac = WB0 + kc * 32768u;
            const uint32_t Bc = H2 + kc * 8192u;
            uint32_t a[4][4];
            #pragma unroll
            for (int kk = 0; kk < 4; kk++)
                ldsm4(a[kk], addrA(Ac, mbase, kk * 2, lane));
            #pragma unroll
            for (int j2 = 0; j2 < 4; j2++) {
                #pragma unroll
                for (int kk = 0; kk < 4; kk++) {
                    uint32_t bf[4];
                    ldsm4t(bf, addrA(Bc, kk * 16, j2 * 2, lane));
                    mma16816(sacc[2 * j2],     a[kk], bf[0], bf[1]);
                    mma16816(sacc[2 * j2 + 1], a[kk], bf[2], bf[3]);
                }
            }
        }

        const int mA = mbase + (lane >> 2);
        const int mB = mA + 8;
        const float bA = b3[mA], bB = b3[mB];
        float sA = 0.0f, sB = 0.0f;
        #pragma unroll
        for (int j = 0; j < 8; j++) {
            const int nl = s0 + j * 8 + (lane & 3) * 2;
            float v0 = sacc[j][0] + bA, v1x = sacc[j][1] + bA;
            float v2x = sacc[j][2] + bB, v3 = sacc[j][3] + bB;
            float2 f0 = {v0, v1x}, f1 = {v2x, v3};
            *(float2*)&of[(size_t)mA * NSEQ + nl] = f0;
            *(float2*)&of[(size_t)mB * NSEQ + nl] = f1;
            sA += v0 + v1x; sB += v2x + v3;
        }
        sA += __shfl_xor_sync(0xffffffffu, sA, 1);
        sA += __shfl_xor_sync(0xffffffffu, sA, 2);
        sB += __shfl_xor_sync(0xffffffffu, sB, 1);
        sB += __shfl_xor_sync(0xffffffffu, sB, 2);
        if ((lane & 3) == 0) {
            atomicAdd(&g_chansum[b * C_DIM + mA], sA);
            atomicAdd(&g_chansum[b * C_DIM + mB], sB);
        }
    }
}

// ---------------- final: parallelized SE gate + residual ----------------
__global__ void final_kernel(const float* __restrict__ feat,
                             const float* __restrict__ Wse1, const float* __restrict__ bse1,
                             const float* __restrict__ Wse2, const float* __restrict__ bse2,
                             float* __restrict__ out)
{
    __shared__ float sq[BS * C_DIM];
    __shared__ float fcp[BS * 16][8];
    __shared__ float fc[BS * 16];
    __shared__ float gate[BS * C_DIM];
    const int tid = threadIdx.x;
    const float invn = 1.0f / (float)NSEQ;

    for (int e = tid; e < BS * C_DIM; e += blockDim.x)
        sq[e] = g_chansum[e] * invn;
    __syncthreads();

    // fc1: 32 (b,r) pairs x 8 chunk-partials — all 256 threads active
    {
        const int pair = tid >> 3, chunk = tid & 7;
        const int b = pair >> 4, r = pair & 15;
        const float* wrow = Wse1 + r * C_DIM + chunk * 32;
        const float* sqb = sq + b * C_DIM + chunk * 32;
        float a = 0.0f;
        #pragma unroll
        for (int c = 0; c < 32; c++) a += sqb[c] * wrow[c];
        fcp[pair][chunk] = a;
    }
    __syncthreads();
    if (tid < BS * 16) {
        float a = bse1[tid & 15];
        #pragma unroll
        for (int k = 0; k < 8; k++) a += fcp[tid][k];
        fc[tid] = fmaxf(a, 0.0f);
    }
    __syncthreads();

    for (int e = tid; e < BS * C_DIM; e += blockDim.x) {
        int b = e >> 8, c = e & 255;
        float a = bse2[c];
        #pragma unroll
        for (int r = 0; r < 16; r++) a += fc[b * 16 + r] * Wse2[c * 16 + r];
        gate[e] = 1.0f / (1.0f + __expf(-a));
    }
    __syncthreads();

    const int total4 = BS * C_DIM * NSEQ / 4;
    for (int i = blockIdx.x * blockDim.x + tid; i < total4; i += gridDim.x * blockDim.x) {
        int ch = i >> 10;
        float gv = gate[ch];
        float4 f = ((const float4*)feat)[i];
        float4 m = ((const float4*)g_msg2)[i];
        float4 o;
        o.x = f.x + m.x * gv;
        o.y = f.y + m.y * gv;
        o.z = f.z + m.z * gv;
        o.w = f.w + m.w * gv;
        ((float4*)out)[i] = o;
    }
}

// ---------------- launch ----------------
extern "C" void kernel_launch(void* const* d_in, const int* in_sizes, int n_in,
                              void* d_out, int out_size)
{
    const float* feat = (const float*)d_in[0];
    const float* Wq = (const float*)d_in[1];  const float* bq = (const float*)d_in[2];
    const float* Wk = (const float*)d_in[3];  const float* bk = (const float*)d_in[4];
    const float* Wv = (const float*)d_in[5];  const float* bv = (const float*)d_in[6];
    const float* W1 = (const float*)d_in[7];  const float* b1 = (const float*)d_in[8];
    const float* g1 = (const float*)d_in[9];  const float* be1 = (const float*)d_in[10];
    const float* m1 = (const float*)d_in[11]; const float* v1 = (const float*)d_in[12];
    const float* W2 = (const float*)d_in[13]; const float* b2 = (const float*)d_in[14];
    const float* g2 = (const float*)d_in[15]; const float* be2 = (const float*)d_in[16];
    const float* m2 = (const float*)d_in[17]; const float* v2 = (const float*)d_in[18];
    const float* W3 = (const float*)d_in[19]; const float* b3 = (const float*)d_in[20];
    const float* Wse1 = (const float*)d_in[21]; const float* bse1 = (const float*)d_in[22];
    const float* Wse2 = (const float*)d_in[23]; const float* bse2 = (const float*)d_in[24];

    __nv_bfloat16 *featbfp, *Wbfp, *Qtp, *Ktp, *Vcp, *xdp;
    float *msg2p;
    cudaGetSymbolAddress((void**)&featbfp, g_featbf);
    cudaGetSymbolAddress((void**)&Wbfp, g_Wbf);
    cudaGetSymbolAddress((void**)&Qtp, g_Qt);
    cudaGetSymbolAddress((void**)&Ktp, g_Kt);
    cudaGetSymbolAddress((void**)&Vcp, g_Vc);
    cudaGetSymbolAddress((void**)&xdp, g_xdiff);
    cudaGetSymbolAddress((void**)&msg2p, g_msg2);

    static bool attr_set = false;
    if (!attr_set) {
        cudaFuncSetAttribute(qkv_kernel, cudaFuncAttributeMaxDynamicSharedMemorySize, 65536);
        cudaFuncSetAttribute(flash_mma, cudaFuncAttributeMaxDynamicSharedMemorySize, 81920);
        cudaFuncSetAttribute(fused_mlp, cudaFuncAttributeMaxDynamicSharedMemorySize, 196608);
        attr_set = true;
    }

    convert_all<<<4096, 256>>>(feat, Wq, Wk, Wv, W1, W2, W3);

    qkv_kernel<<<dim3(32, 8, 2), 256, 65536>>>(Wbfp + WOFF_Q, Wbfp + WOFF_K, Wbfp + WOFF_V,
                                               featbfp, bq, bk, bv, Qtp, Ktp, Vcp);

    flash_mma<<<dim3(NSEQ / 128, BS * NH), 256, 81920>>>(Qtp, Ktp, Vcp, feat, xdp);

    fused_mlp<<<dim3(64, 2), 256, 196608>>>(Wbfp, xdp,
                                            b1, g1, be1, m1, v1,
                                            b2, g2, be2, m2, v2,
                                            b3, msg2p);

    final_kernel<<<296, 256>>>(feat, Wse1, bse1, Wse2, bse2, (float*)d_out);
}

// round 15
// speedup vs baseline: 1.0526x; 1.0526x over previous
#include <cuda_runtime.h>
#include <cuda_bf16.h>
#include <math.h>
#include <stdint.h>

#define C_DIM 256
#define CH_DIM 128
#define NSEQ 4096
#define BS 2
#define DH 64
#define NH 4
#define EPS 1e-5f
#define C1F 0.1803368801111204f   // 0.125 * log2(e)

// weight pack offsets (elements)
#define WOFF_Q 0
#define WOFF_K 65536
#define WOFF_V 131072
#define WOFF_1 196608
#define WOFF_2 229376
#define WOFF_3 245760
#define WTOT   278528

// ---------------- scratch ----------------
__device__ __align__(128) __nv_bfloat16 g_featbf[BS * C_DIM * NSEQ];
__device__ __align__(128) __nv_bfloat16 g_Wbf[WTOT];
__device__ __align__(128) __nv_bfloat16 g_Qt[BS * C_DIM * NSEQ];   // [bh][n][64] (pre-scaled by C1)
__device__ __align__(128) __nv_bfloat16 g_Kt[BS * C_DIM * NSEQ];   // [bh][n][64]
__device__ __align__(128) __nv_bfloat16 g_Vc[BS * C_DIM * NSEQ];   // [b][256][4096]
__device__ __align__(128) __nv_bfloat16 g_xdiff[BS * C_DIM * NSEQ];
__device__ float g_msg2[BS * C_DIM * NSEQ];
__device__ float g_chansum[BS * C_DIM];
__device__ float g_gate[BS * C_DIM];

// ---------------- PTX helpers ----------------
__device__ __forceinline__ uint32_t s2u(const void* p) {
    uint32_t a;
    asm("{ .reg .u64 t; cvta.to.shared.u64 t, %1; cvt.u32.u64 %0, t; }" : "=r"(a) : "l"(p));
    return a;
}
__device__ __forceinline__ uint32_t sw128(uint32_t x) { return x ^ ((x >> 3) & 0x70); }

__device__ __forceinline__ void cpa16(uint32_t s, const void* g) {
    asm volatile("cp.async.cg.shared.global [%0], [%1], 16;" :: "r"(s), "l"(g));
}
__device__ __forceinline__ void cpa_commit() { asm volatile("cp.async.commit_group;" ::: "memory"); }
__device__ __forceinline__ void cpa_wait1()  { asm volatile("cp.async.wait_group 1;" ::: "memory"); }
__device__ __forceinline__ void cpa_wait0()  { asm volatile("cp.async.wait_group 0;" ::: "memory"); }

__device__ __forceinline__ void ldsm4(uint32_t r[4], uint32_t addr) {
    asm volatile("ldmatrix.sync.aligned.m8n8.x4.shared.b16 {%0,%1,%2,%3}, [%4];"
                 : "=r"(r[0]), "=r"(r[1]), "=r"(r[2]), "=r"(r[3]) : "r"(addr));
}
__device__ __forceinline__ void ldsm4t(uint32_t r[4], uint32_t addr) {
    asm volatile("ldmatrix.sync.aligned.m8n8.x4.trans.shared.b16 {%0,%1,%2,%3}, [%4];"
                 : "=r"(r[0]), "=r"(r[1]), "=r"(r[2]), "=r"(r[3]) : "r"(addr));
}

__device__ __forceinline__ void mma16816(float d[4], const uint32_t a[4], uint32_t b0, uint32_t b1) {
    asm volatile(
        "mma.sync.aligned.m16n8k16.row.col.f32.bf16.bf16.f32 "
        "{%0,%1,%2,%3}, {%4,%5,%6,%7}, {%8,%9}, {%0,%1,%2,%3};"
        : "+f"(d[0]), "+f"(d[1]), "+f"(d[2]), "+f"(d[3])
        : "r"(a[0]), "r"(a[1]), "r"(a[2]), "r"(a[3]), "r"(b0), "r"(b1));
}

__device__ __forceinline__ float ex2f(float x) {
    float y; asm("ex2.approx.ftz.f32 %0, %1;" : "=f"(y) : "f"(x)); return y;
}
__device__ __forceinline__ uint32_t packbf2(float lo, float hi) {
    __nv_bfloat162 h = __floats2bfloat162_rn(lo, hi);
    return *(uint32_t*)&h;
}

__device__ __forceinline__ uint32_t addrA(uint32_t base, int row0, int seg0, int lane) {
    int g = lane >> 3, i = lane & 7;
    int r = row0 + i + ((g & 1) << 3);
    int s = seg0 + (g >> 1);
    return base + sw128((uint32_t)(r * 128 + s * 16));
}
__device__ __forceinline__ uint32_t addrB(uint32_t base, int row0, int seg0, int lane) {
    int g = lane >> 3, i = lane & 7;
    int r = row0 + i + ((g >> 1) << 3);
    int s = seg0 + (g & 1);
    return base + sw128((uint32_t)(r * 128 + s * 16));
}

// ---------------- converts (merged, + chansum zero) ----------------
__global__ void convert_all(const float* __restrict__ feat,
                            const float* __restrict__ Wq, const float* __restrict__ Wk,
                            const float* __restrict__ Wv, const float* __restrict__ W1,
                            const float* __restrict__ W2, const float* __restrict__ W3) {
    int i = blockIdx.x * blockDim.x + threadIdx.x;
    if (i < BS * C_DIM) g_chansum[i] = 0.0f;
    const int tot2 = BS * C_DIM * NSEQ / 2;
    if (i < tot2) {
        float2 v = ((const float2*)feat)[i];
        ((__nv_bfloat162*)g_featbf)[i] = __floats2bfloat162_rn(v.x, v.y);
    }
    if (i < WTOT) {
        float v;
        if      (i < WOFF_K) v = Wq[i - WOFF_Q];
        else if (i < WOFF_V) v = Wk[i - WOFF_K];
        else if (i < WOFF_1) v = Wv[i - WOFF_V];
        else if (i < WOFF_2) v = W1[i - WOFF_1];
        else if (i < WOFF_3) v = W2[i - WOFF_2];
        else                 v = W3[i - WOFF_3];
        g_Wbf[i] = __float2bfloat16(v);
    }
}

// ---------------- qkv fused: single-barrier pipelines in both branches ----------------
__global__ __launch_bounds__(256, 2) void qkv_kernel(
    const __nv_bfloat16* __restrict__ Wqb, const __nv_bfloat16* __restrict__ Wkb,
    const __nv_bfloat16* __restrict__ Wvb, const __nv_bfloat16* __restrict__ X,
    const float* __restrict__ bq, const float* __restrict__ bk, const float* __restrict__ bv,
    __nv_bfloat16* __restrict__ outQ, __nv_bfloat16* __restrict__ outK,
    __nv_bfloat16* __restrict__ outV)
{
    extern __shared__ __align__(128) __nv_bfloat16 dyns[];
    const int tid = threadIdx.x, lane = tid & 31, w = tid >> 5;
    const int b = blockIdx.z;
    const __nv_bfloat16* Xb = X + (size_t)b * C_DIM * NSEQ;
    const uint32_t base = s2u(dyns);

    if (blockIdx.y < 4) {
        const int s0 = blockIdx.x * 128, ch0 = blockIdx.y * 64;

        auto load_stage = [&](int st, int k0) {
            const uint32_t Xa = base + st * 16384u;
            const uint32_t Qa = base + 32768u + st * 8192u;
            const uint32_t Ka = base + 49152u + st * 8192u;
            #pragma unroll
            for (int i = 0; i < 4; i++) {
                int e = tid + i * 256; int r = e >> 4, c = e & 15;
                int h = c >> 3, sg = c & 7;
                cpa16(Xa + h * 8192u + sw128((uint32_t)(r * 128 + sg * 16)),
                      Xb + (size_t)(k0 + r) * NSEQ + s0 + h * 64 + sg * 8);
            }
            #pragma unroll
            for (int i = 0; i < 2; i++) {
                int e = tid + i * 256; int r = e >> 3, sg = e & 7;
                cpa16(Qa + sw128((uint32_t)(r * 128 + sg * 16)), Wqb + (size_t)(ch0 + r) * 256 + k0 + sg * 8);
                cpa16(Ka + sw128((uint32_t)(r * 128 + sg * 16)), Wkb + (size_t)(ch0 + r) * 256 + k0 + sg * 8);
            }
        };

        load_stage(0, 0);
        cpa_commit();

        float qacc[8][4], kacc[8][4];
        #pragma unroll
        for (int j = 0; j < 8; j++)
            #pragma unroll
            for (int x = 0; x < 4; x++) { qacc[j][x] = 0.0f; kacc[j][x] = 0.0f; }

        for (int kt = 0; kt < 4; kt++) {
            cpa_wait0();
            __syncthreads();
            if (kt + 1 < 4) {
                load_stage((kt + 1) & 1, (kt + 1) * 64);
                cpa_commit();
            }

            const int st = kt & 1;
            const uint32_t Xh = base + st * 16384u + (w >> 2) * 8192u;
            const uint32_t Qa = base + 32768u + st * 8192u;
            const uint32_t Ka = base + 49152u + st * 8192u;

            uint32_t a[4][4];
            #pragma unroll
            for (int kk = 0; kk < 4; kk++)
                ldsm4t(a[kk], addrB(Xh, kk * 16, (w & 3) * 2, lane));

            #pragma unroll
            for (int j2 = 0; j2 < 4; j2++) {
                #pragma unroll
                for (int kk = 0; kk < 4; kk++) {
                    uint32_t bf[4];
                    ldsm4(bf, addrB(Qa, j2 * 16, kk * 2, lane));
                    mma16816(qacc[2 * j2],     a[kk], bf[0], bf[1]);
                    mma16816(qacc[2 * j2 + 1], a[kk], bf[2], bf[3]);
                }
                #pragma unroll
                for (int kk = 0; kk < 4; kk++) {
                    uint32_t bf[4];
                    ldsm4(bf, addrB(Ka, j2 * 16, kk * 2, lane));
                    mma16816(kacc[2 * j2],     a[kk], bf[0], bf[1]);
                    mma16816(kacc[2 * j2 + 1], a[kk], bf[2], bf[3]);
                }
            }
        }

        const int qA = s0 + w * 16 + (lane >> 2);
        const int qB = qA + 8;
        const size_t obo = ((size_t)(b * NH + blockIdx.y) * NSEQ) * 64;
        __nv_bfloat16* obQ = outQ + obo;
        __nv_bfloat16* obK = outK + obo;
        #pragma unroll
        for (int j = 0; j < 8; j++) {
            const int chl = j * 8 + (lane & 3) * 2;
            float2 bbq = *(const float2*)&bq[ch0 + chl];
            float2 bbk = *(const float2*)&bk[ch0 + chl];
            *(uint32_t*)&obQ[(size_t)qA * 64 + chl] = packbf2((qacc[j][0] + bbq.x) * C1F, (qacc[j][1] + bbq.y) * C1F);
            *(uint32_t*)&obQ[(size_t)qB * 64 + chl] = packbf2((qacc[j][2] + bbq.x) * C1F, (qacc[j][3] + bbq.y) * C1F);
            *(uint32_t*)&obK[(size_t)qA * 64 + chl] = packbf2(kacc[j][0] + bbk.x, kacc[j][1] + bbk.y);
            *(uint32_t*)&obK[(size_t)qB * 64 + chl] = packbf2(kacc[j][2] + bbk.x, kacc[j][3] + bbk.y);
        }
    } else {
        const int n0 = blockIdx.x * 128, m0 = (blockIdx.y - 4) * 64;
        const int mw = w & 3, nw = w >> 2;

        auto load_stage = [&](int st, int k0) {
            const uint32_t Aa = base + st * 24576u;
            const uint32_t Ba = Aa + 8192u;
            #pragma unroll
            for (int i = 0; i < 2; i++) {
                int e = tid + i * 256; int r = e >> 3, sg = e & 7;
                cpa16(Aa + sw128((uint32_t)(r * 128 + sg * 16)), Wvb + (size_t)(m0 + r) * 256 + k0 + sg * 8);
            }
            #pragma unroll
            for (int i = 0; i < 4; i++) {
                int e = tid + i * 256; int r = e >> 4, c = e & 15;
                int h = c >> 3, sg = c & 7;
                cpa16(Ba + h * 8192u + sw128((uint32_t)(r * 128 + sg * 16)),
                      Xb + (size_t)(k0 + r) * NSEQ + n0 + h * 64 + sg * 8);
            }
        };

        load_stage(0, 0);
        cpa_commit();

        float sacc[8][4];
        #pragma unroll
        for (int j = 0; j < 8; j++)
            #pragma unroll
            for (int x = 0; x < 4; x++) sacc[j][x] = 0.0f;

        for (int kt = 0; kt < 4; kt++) {
            cpa_wait0();
            __syncthreads();
            if (kt + 1 < 4) {
                load_stage((kt + 1) & 1, (kt + 1) * 64);
                cpa_commit();
            }

            const uint32_t Aa = base + (kt & 1) * 24576u;
            const uint32_t Bh = Aa + 8192u + nw * 8192u;

            uint32_t a[4][4];
            #pragma unroll
            for (int kk = 0; kk < 4; kk++)
                ldsm4(a[kk], addrA(Aa, mw * 16, kk * 2, lane));

            #pragma unroll
            for (int j2 = 0; j2 < 4; j2++) {
                #pragma unroll
                for (int kk = 0; kk < 4; kk++) {
                    uint32_t bf[4];
                    ldsm4t(bf, addrA(Bh, kk * 16, j2 * 2, lane));
                    mma16816(sacc[2 * j2],     a[kk], bf[0], bf[1]);
                    mma16816(sacc[2 * j2 + 1], a[kk], bf[2], bf[3]);
                }
            }
        }

        const int mA = m0 + mw * 16 + (lane >> 2);
        const int mB = mA + 8;
        const float biasA = bv[mA], biasB = bv[mB];
        __nv_bfloat16* ob = outV + (size_t)b * C_DIM * NSEQ;
        #pragma unroll
        for (int j = 0; j < 8; j++) {
            const int nl = n0 + nw * 64 + j * 8 + (lane & 3) * 2;
            *(uint32_t*)&ob[(size_t)mA * NSEQ + nl] = packbf2(sacc[j][0] + biasA, sacc[j][1] + biasA);
            *(uint32_t*)&ob[(size_t)mB * NSEQ + nl] = packbf2(sacc[j][2] + biasB, sacc[j][3] + biasB);
        }
    }
}

// ---------------- flash attention (R13 best: single barrier per iteration) ----------------
__global__ __launch_bounds__(256, 2) void flash_mma(
    const __nv_bfloat16* __restrict__ Qt,
    const __nv_bfloat16* __restrict__ Kt,
    const __nv_bfloat16* __restrict__ Vc,
    const float* __restrict__ feat,
    __nv_bfloat16* __restrict__ xdiff)
{
    extern __shared__ __align__(128) __nv_bfloat16 fsm[];
    const uint32_t base = s2u(fsm);

    const int tid = threadIdx.x;
    const int lane = tid & 31;
    const int w = tid >> 5;
    const int bh = blockIdx.y;
    const int q0 = blockIdx.x * 128;

    const uint32_t QSa = base;

    const __nv_bfloat16* Qg = Qt + (size_t)bh * NSEQ * 64;
    const __nv_bfloat16* Kg = Kt + (size_t)bh * NSEQ * 64;
    const __nv_bfloat16* Vg = Vc + (size_t)bh * 64 * NSEQ;

    auto load_kv = [&](int st, int k0) {
        const uint32_t KS = base + 16384u + (uint32_t)st * 32768u;
        const uint32_t VS = KS + 16384u;
        #pragma unroll
        for (int i = 0; i < 4; i++) {
            int e = tid + i * 256;
            int row = e >> 3, sg = e & 7;
            cpa16(KS + sw128((uint32_t)(row * 128 + sg * 16)), Kg + (size_t)(k0 + row) * 64 + sg * 8);
        }
        #pragma unroll
        for (int i = 0; i < 4; i++) {
            int e = tid + i * 256;
            int c = e >> 4, rem = e & 15;
            int p = rem >> 3, sg = rem & 7;
            cpa16(VS + p * 8192u + sw128((uint32_t)(c * 128 + sg * 16)),
                  Vg + (size_t)c * NSEQ + k0 + p * 64 + sg * 8);
        }
    };

    #pragma unroll
    for (int i = 0; i < 4; i++) {
        int e = tid + i * 256;
        int row = e >> 3, sg = e & 7;
        cpa16(QSa + sw128((uint32_t)(row * 128 + sg * 16)), Qg + (size_t)(q0 + row) * 64 + sg * 8);
    }
    load_kv(0, 0);
    cpa_commit();

    float l_lo = 0.0f, l_hi = 0.0f;
    float oacc[8][4];
    #pragma unroll
    for (int j = 0; j < 8; j++)
        #pragma unroll
        for (int x = 0; x < 4; x++) oacc[j][x] = 0.0f;
    uint32_t qa[4][4];

    for (int t = 0; t < 32; t++) {
        const int cur = t & 1;
        cpa_wait0();
        __syncthreads();

        if (t + 1 < 32) {
            load_kv(1 - cur, (t + 1) * 128);
            cpa_commit();
        }

        if (t == 0) {
            #pragma unroll
            for (int kk = 0; kk < 4; kk++)
                ldsm4(qa[kk], addrA(QSa, w * 16, kk * 2, lane));
        }

        const uint32_t KS = base + 16384u + (uint32_t)cur * 32768u;
        const uint32_t VS = KS + 16384u;

        #pragma unroll
        for (int j2 = 0; j2 < 8; j2++) {
            float s0a[4] = {0.0f, 0.0f, 0.0f, 0.0f};
            float s1a[4] = {0.0f, 0.0f, 0.0f, 0.0f};
            #pragma unroll
            for (int kk = 0; kk < 4; kk++) {
                uint32_t bq[4];
                ldsm4(bq, addrB(KS, j2 * 16, kk * 2, lane));
                mma16816(s0a, qa[kk], bq[0], bq[1]);
                mma16816(s1a, qa[kk], bq[2], bq[3]);
            }

            uint32_t a[4];
            {
                float p0 = ex2f(s0a[0]);
                float p1 = ex2f(s0a[1]);
                float p2 = ex2f(s0a[2]);
                float p3 = ex2f(s0a[3]);
                l_lo += p0 + p1; l_hi += p2 + p3;
                a[0] = packbf2(p0, p1);
                a[1] = packbf2(p2, p3);
                float p4 = ex2f(s1a[0]);
                float p5 = ex2f(s1a[1]);
                float p6 = ex2f(s1a[2]);
                float p7 = ex2f(s1a[3]);
                l_lo += p4 + p5; l_hi += p6 + p7;
                a[2] = packbf2(p4, p5);
                a[3] = packbf2(p6, p7);
            }

            const uint32_t Vp = VS + (uint32_t)(j2 >> 2) * 8192u;
            const int seg0 = (j2 & 3) * 2;
            #pragma unroll
            for (int cp = 0; cp < 4; cp++) {
                uint32_t bv4[4];
                ldsm4(bv4, addrB(Vp, cp * 16, seg0, lane));
                mma16816(oacc[2 * cp],     a, bv4[0], bv4[1]);
                mma16816(oacc[2 * cp + 1], a, bv4[2], bv4[3]);
            }
        }
    }

    l_lo += __shfl_xor_sync(0xffffffffu, l_lo, 1);
    l_lo += __shfl_xor_sync(0xffffffffu, l_lo, 2);
    l_hi += __shfl_xor_sync(0xffffffffu, l_hi, 1);
    l_hi += __shfl_xor_sync(0xffffffffu, l_hi, 2);
    const float inv_lo = 1.0f / l_lo;
    const float inv_hi = 1.0f / l_hi;

    __nv_bfloat16* Ms = fsm + 8192;
    const int qrl = w * 16 + (lane >> 2);
    #pragma unroll
    for (int ct = 0; ct < 8; ct++) {
        const int ch = ct * 8 + (lane & 3) * 2;
        Ms[ch * 136 + qrl]           = __float2bfloat16(oacc[ct][0] * inv_lo);
        Ms[(ch + 1) * 136 + qrl]     = __float2bfloat16(oacc[ct][1] * inv_lo);
        Ms[ch * 136 + qrl + 8]       = __float2bfloat16(oacc[ct][2] * inv_hi);
        Ms[(ch + 1) * 136 + qrl + 8] = __float2bfloat16(oacc[ct][3] * inv_hi);
    }
    __syncthreads();

    const float* fg = feat + (size_t)bh * 64 * NSEQ;
    __nv_bfloat16* xd = xdiff + (size_t)bh * 64 * NSEQ;
    #pragma unroll
    for (int i = 0; i < 16; i++) {
        int idx = tid + i * 256;
        int ch = idx >> 6, qp = (idx & 63) * 2;
        float2 f = *(const float2*)&fg[(size_t)ch * NSEQ + q0 + qp];
        float m0v = __bfloat162float(Ms[ch * 136 + qp]);
        float m1v = __bfloat162float(Ms[ch * 136 + qp + 1]);
        *(uint32_t*)&xd[(size_t)ch * NSEQ + q0 + qp] = packbf2(f.x - m0v, f.y - m1v);
    }
}

// ---------------- fused MLP (unchanged) ----------------
__device__ __forceinline__ void mlp_load_W(uint32_t dst, const __nv_bfloat16* W, int M, int K, int tid) {
    const int chunks = K >> 6;
    const int per_chunk = M * 8;
    const int total = chunks * per_chunk;
    for (int u = tid; u < total; u += 256) {
        int kc = u / per_chunk;
        int rem = u - kc * per_chunk;
        int m = rem >> 3, sg = rem & 7;
        cpa16(dst + (uint32_t)(kc * M * 128) + sw128((uint32_t)(m * 128 + sg * 16)),
              W + (size_t)m * K + kc * 64 + sg * 8);
    }
}

__global__ __launch_bounds__(256) void fused_mlp(
    const __nv_bfloat16* __restrict__ Wb,
    const __nv_bfloat16* __restrict__ xdiff,
    const float* __restrict__ b1, const float* __restrict__ g1, const float* __restrict__ be1,
    const float* __restrict__ m1, const float* __restrict__ v1,
    const float* __restrict__ b2, const float* __restrict__ g2, const float* __restrict__ be2,
    const float* __restrict__ m2, const float* __restrict__ v2,
    const float* __restrict__ b3,
    float* __restrict__ msg2)
{
    extern __shared__ __align__(128) __nv_bfloat16 dyns[];
    const int tid = threadIdx.x, lane = tid & 31, w = tid >> 5;
    const int s0 = blockIdx.x * 64, b = blockIdx.y;
    const uint32_t base = s2u(dyns);
    const uint32_t XD = base, H1 = base + 32768u, H2 = base + 49152u;
    const uint32_t WB0 = base + 65536u, WB1 = base + 131072u;

    const __nv_bfloat16* xd_g = xdiff + (size_t)b * C_DIM * NSEQ;

    for (int u = tid; u < 2048; u += 256) {
        int r = u >> 3, sg = u & 7;
        cpa16(XD + sw128((uint32_t)(r * 128 + sg * 16)), xd_g + (size_t)r * NSEQ + s0 + sg * 8);
    }
    mlp_load_W(WB0, Wb + WOFF_1, 128, 256, tid);
    cpa_commit();
    mlp_load_W(WB1, Wb + WOFF_2, 128, 128, tid);
    cpa_commit();

    cpa_wait1();
    __syncthreads();

    {
        float sacc[8][4];
        #pragma unroll
        for (int j = 0; j < 8; j++)
            #pragma unroll
            for (int x = 0; x < 4; x++) sacc[j][x] = 0.0f;

        for (int kc = 0; kc < 4; kc++) {
            const uint32_t Ac = WB0 + kc * 16384u;
            const uint32_t Bc = XD + kc * 8192u;
            uint32_t a[4][4];
            #pragma unroll
            for (int kk = 0; kk < 4; kk++)
                ldsm4(a[kk], addrA(Ac, w * 16, kk * 2, lane));
            #pragma unroll
            for (int j2 = 0; j2 < 4; j2++) {
                #pragma unroll
                for (int kk = 0; kk < 4; kk++) {
                    uint32_t bf[4];
                    ldsm4t(bf, addrA(Bc, kk * 16, j2 * 2, lane));
                    mma16816(sacc[2 * j2],     a[kk], bf[0], bf[1]);
                    mma16816(sacc[2 * j2 + 1], a[kk], bf[2], bf[3]);
                }
            }
        }

        const int mA = w * 16 + (lane >> 2);
        const int mB = mA + 8;
        float scA = g1[mA] * rsqrtf(v1[mA] + EPS), shA = be1[mA] - m1[mA] * scA;
        float scB = g1[mB] * rsqrtf(v1[mB] + EPS), shB = be1[mB] - m1[mB] * scB;
        const float bA = b1[mA], bB = b1[mB];
        #pragma unroll
        for (int j = 0; j < 8; j++) {
            const int nl = j * 8 + (lane & 3) * 2;
            float v0 = fmaxf((sacc[j][0] + bA) * scA + shA, 0.0f);
            float v1x = fmaxf((sacc[j][1] + bA) * scA + shA, 0.0f);
            float v2x = fmaxf((sacc[j][2] + bB) * scB + shB, 0.0f);
            float v3 = fmaxf((sacc[j][3] + bB) * scB + shB, 0.0f);
            *(uint32_t*)((char*)dyns + (H1 - base) + sw128((uint32_t)(mA * 128 + nl * 2))) = packbf2(v0, v1x);
            *(uint32_t*)((char*)dyns + (H1 - base) + sw128((uint32_t)(mB * 128 + nl * 2))) = packbf2(v2x, v3);
        }
    }
    __syncthreads();

    mlp_load_W(WB0, Wb + WOFF_3, 256, 128, tid);
    cpa_commit();

    cpa_wait1();
    __syncthreads();

    {
        float sacc[8][4];
        #pragma unroll
        for (int j = 0; j < 8; j++)
            #pragma unroll
            for (int x = 0; x < 4; x++) sacc[j][x] = 0.0f;

        for (int kc = 0; kc < 2; kc++) {
            const uint32_t Ac = WB1 + kc * 16384u;
            const uint32_t Bc = H1 + kc * 8192u;
            uint32_t a[4][4];
            #pragma unroll
            for (int kk = 0; kk < 4; kk++)
                ldsm4(a[kk], addrA(Ac, w * 16, kk * 2, lane));
            #pragma unroll
            for (int j2 = 0; j2 < 4; j2++) {
                #pragma unroll
                for (int kk = 0; kk < 4; kk++) {
                    uint32_t bf[4];
                    ldsm4t(bf, addrA(Bc, kk * 16, j2 * 2, lane));
                    mma16816(sacc[2 * j2],     a[kk], bf[0], bf[1]);
                    mma16816(sacc[2 * j2 + 1], a[kk], bf[2], bf[3]);
                }
            }
        }

        const int mA = w * 16 + (lane >> 2);
        const int mB = mA + 8;
        float scA = g2[mA] * rsqrtf(v2[mA] + EPS), shA = be2[mA] - m2[mA] * scA;
        float scB = g2[mB] * rsqrtf(v2[mB] + EPS), shB = be2[mB] - m2[mB] * scB;
        const float bA = b2[mA], bB = b2[mB];
        #pragma unroll
        for (int j = 0; j < 8; j++) {
            const int nl = j * 8 + (lane & 3) * 2;
            float v0 = fmaxf((sacc[j][0] + bA) * scA + shA, 0.0f);
            float v1x = fmaxf((sacc[j][1] + bA) * scA + shA, 0.0f);
            float v2x = fmaxf((sacc[j][2] + bB) * scB + shB, 0.0f);
            float v3 = fmaxf((sacc[j][3] + bB) * scB + shB, 0.0f);
            *(uint32_t*)((char*)dyns + (H2 - base) + sw128((uint32_t)(mA * 128 + nl * 2))) = packbf2(v0, v1x);
            *(uint32_t*)((char*)dyns + (H2 - base) + sw128((uint32_t)(mB * 128 + nl * 2))) = packbf2(v2x, v3);
        }
    }
    __syncthreads();

    cpa_wait0();
    __syncthreads();

    float* of = msg2 + (size_t)b * C_DIM * NSEQ;
    #pragma unroll
    for (int ms = 0; ms < 2; ms++) {
        float sacc[8][4];
        #pragma unroll
        for (int j = 0; j < 8; j++)
            #pragma unroll
            for (int x = 0; x < 4; x++) sacc[j][x] = 0.0f;

        const int mbase = ms * 128 + w * 16;
        for (int kc = 0; kc < 2; kc++) {
            const uint32_t Ac = WB0 + kc * 32768u;
            const uint32_t Bc = H2 + kc * 8192u;
            uint32_t a[4][4];
            #pragma unroll
            for (int kk = 0; kk < 4; kk++)
                ldsm4(a[kk], addrA(Ac, mbase, kk * 2, lane));
            #pragma unroll
            for (int j2 = 0; j2 < 4; j2++) {
                #pragma unroll
                for (int kk = 0; kk < 4; kk++) {
                    uint32_t bf[4];
                    ldsm4t(bf, addrA(Bc, kk * 16, j2 * 2, lane));
                    mma16816(sacc[2 * j2],     a[kk], bf[0], bf[1]);
                    mma16816(sacc[2 * j2 + 1], a[kk], bf[2], bf[3]);
                }
            }
        }

        const int mA = mbase + (lane >> 2);
        const int mB = mA + 8;
        const float bA = b3[mA], bB = b3[mB];
        float sA = 0.0f, sB = 0.0f;
        #pragma unroll
        for (int j = 0; j < 8; j++) {
            const int nl = s0 + j * 8 + (lane & 3) * 2;
            float v0 = sacc[j][0] + bA, v1x = sacc[j][1] + bA;
            float v2x = sacc[j][2] + bB, v3 = sacc[j][3] + bB;
            float2 f0 = {v0, v1x}, f1 = {v2x, v3};
            *(float2*)&of[(size_t)mA * NSEQ + nl] = f0;
            *(float2*)&of[(size_t)mB * NSEQ + nl] = f1;
            sA += v0 + v1x; sB += v2x + v3;
        }
        sA += __shfl_xor_sync(0xffffffffu, sA, 1);
        sA += __shfl_xor_sync(0xffffffffu, sA, 2);
        sB += __shfl_xor_sync(0xffffffffu, sB, 1);
        sB += __shfl_xor_sync(0xffffffffu, sB, 2);
        if ((lane & 3) == 0) {
            atomicAdd(&g_chansum[b * C_DIM + mA], sA);
            atomicAdd(&g_chansum[b * C_DIM + mB], sB);
        }
    }
}

// ---------------- SE gate (separate, confirmed best) ----------------
__global__ void se_kernel(const float* __restrict__ Wse1, const float* __restrict__ bse1,
                          const float* __restrict__ Wse2, const float* __restrict__ bse2)
{
    __shared__ float sq[BS * C_DIM];
    __shared__ float fc[BS * 16];
    const int tid = threadIdx.x;
    const float invn = 1.0f / (float)NSEQ;

    for (int e = tid; e < BS * C_DIM; e += blockDim.x)
        sq[e] = g_chansum[e] * invn;
    __syncthreads();

    if (tid < BS * 16) {
        int b = tid >> 4, r = tid & 15;
        float a = bse1[r];
        for (int c = 0; c < C_DIM; c++) a += sq[b * C_DIM + c] * Wse1[r * C_DIM + c];
        fc[b * 16 + r] = fmaxf(a, 0.0f);
    }
    __syncthreads();

    for (int e = tid; e < BS * C_DIM; e += blockDim.x) {
        int b = e >> 8, c = e & 255;
        float a = bse2[c];
        #pragma unroll
        for (int r = 0; r < 16; r++) a += fc[b * 16 + r] * Wse2[c * 16 + r];
        g_gate[e] = 1.0f / (1.0f + __expf(-a));
    }
}

// ---------------- final residual ----------------
__global__ void final_kernel(const float* __restrict__ feat, float* __restrict__ out)
{
    int i = blockIdx.x * blockDim.x + threadIdx.x;
    const int total4 = BS * C_DIM * NSEQ / 4;
    if (i >= total4) return;
    int ch = i >> 10;
    float gv = g_gate[ch];
    float4 f = ((const float4*)feat)[i];
    float4 m = ((const float4*)g_msg2)[i];
    float4 o;
    o.x = f.x + m.x * gv;
    o.y = f.y + m.y * gv;
    o.z = f.z + m.z * gv;
    o.w = f.w + m.w * gv;
    ((float4*)out)[i] = o;
}

// ---------------- launch ----------------
extern "C" void kernel_launch(void* const* d_in, const int* in_sizes, int n_in,
                              void* d_out, int out_size)
{
    const float* feat = (const float*)d_in[0];
    const float* Wq = (const float*)d_in[1];  const float* bq = (const float*)d_in[2];
    const float* Wk = (const float*)d_in[3];  const float* bk = (const float*)d_in[4];
    const float* Wv = (const float*)d_in[5];  const float* bv = (const float*)d_in[6];
    const float* W1 = (const float*)d_in[7];  const float* b1 = (const float*)d_in[8];
    const float* g1 = (const float*)d_in[9];  const float* be1 = (const float*)d_in[10];
    const float* m1 = (const float*)d_in[11]; const float* v1 = (const float*)d_in[12];
    const float* W2 = (const float*)d_in[13]; const float* b2 = (const float*)d_in[14];
    const float* g2 = (const float*)d_in[15]; const float* be2 = (const float*)d_in[16];
    const float* m2 = (const float*)d_in[17]; const float* v2 = (const float*)d_in[18];
    const float* W3 = (const float*)d_in[19]; const float* b3 = (const float*)d_in[20];
    const float* Wse1 = (const float*)d_in[21]; const float* bse1 = (const float*)d_in[22];
    const float* Wse2 = (const float*)d_in[23]; const float* bse2 = (const float*)d_in[24];

    __nv_bfloat16 *featbfp, *Wbfp, *Qtp, *Ktp, *Vcp, *xdp;
    float *msg2p;
    cudaGetSymbolAddress((void**)&featbfp, g_featbf);
    cudaGetSymbolAddress((void**)&Wbfp, g_Wbf);
    cudaGetSymbolAddress((void**)&Qtp, g_Qt);
    cudaGetSymbolAddress((void**)&Ktp, g_Kt);
    cudaGetSymbolAddress((void**)&Vcp, g_Vc);
    cudaGetSymbolAddress((void**)&xdp, g_xdiff);
    cudaGetSymbolAddress((void**)&msg2p, g_msg2);

    static bool attr_set = false;
    if (!attr_set) {
        cudaFuncSetAttribute(qkv_kernel, cudaFuncAttributeMaxDynamicSharedMemorySize, 65536);
        cudaFuncSetAttribute(flash_mma, cudaFuncAttributeMaxDynamicSharedMemorySize, 81920);
        cudaFuncSetAttribute(fused_mlp, cudaFuncAttributeMaxDynamicSharedMemorySize, 196608);
        attr_set = true;
    }

    convert_all<<<4096, 256>>>(feat, Wq, Wk, Wv, W1, W2, W3);

    qkv_kernel<<<dim3(32, 8, 2), 256, 65536>>>(Wbfp + WOFF_Q, Wbfp + WOFF_K, Wbfp + WOFF_V,
                                               featbfp, bq, bk, bv, Qtp, Ktp, Vcp);

    flash_mma<<<dim3(NSEQ / 128, BS * NH), 256, 81920>>>(Qtp, Ktp, Vcp, feat, xdp);

    fused_mlp<<<dim3(64, 2), 256, 196608>>>(Wbfp, xdp,
                                            b1, g1, be1, m1, v1,
                                            b2, g2, be2, m2, v2,
                                            b3, msg2p);

    se_kernel<<<1, 256>>>(Wse1, bse1, Wse2, bse2);

    const int total4 = BS * C_DIM * NSEQ / 4;
    final_kernel<<<(total4 + 255) / 256, 256>>>(feat, (float*)d_out);
}

// round 16
// speedup vs baseline: 1.0961x; 1.0413x over previous
#include <cuda_runtime.h>
#include <cuda_bf16.h>
#include <math.h>
#include <stdint.h>

#define C_DIM 256
#define CH_DIM 128
#define NSEQ 4096
#define BS 2
#define DH 64
#define NH 4
#define EPS 1e-5f
#define C1F 0.1803368801111204f   // 0.125 * log2(e)

// weight pack offsets (elements)
#define WOFF_Q 0
#define WOFF_K 65536
#define WOFF_V 131072
#define WOFF_1 196608
#define WOFF_2 229376
#define WOFF_3 245760
#define WTOT   278528

// ---------------- scratch ----------------
__device__ __align__(128) __nv_bfloat16 g_featbf[BS * C_DIM * NSEQ];
__device__ __align__(128) __nv_bfloat16 g_Wbf[WTOT];
__device__ __align__(128) __nv_bfloat16 g_Qt[BS * C_DIM * NSEQ];   // [bh][n][64] (pre-scaled by C1)
__device__ __align__(128) __nv_bfloat16 g_Kt[BS * C_DIM * NSEQ];   // [bh][n][64]
__device__ __align__(128) __nv_bfloat16 g_Vc[BS * C_DIM * NSEQ];   // [b][256][4096]
__device__ __align__(128) __nv_bfloat16 g_xdiff[BS * C_DIM * NSEQ];
__device__ float g_msg2[BS * C_DIM * NSEQ];
__device__ float g_chansum[BS * C_DIM];
__device__ float g_gate[BS * C_DIM];

// ---------------- PTX helpers ----------------
__device__ __forceinline__ uint32_t s2u(const void* p) {
    uint32_t a;
    asm("{ .reg .u64 t; cvta.to.shared.u64 t, %1; cvt.u32.u64 %0, t; }" : "=r"(a) : "l"(p));
    return a;
}
__device__ __forceinline__ uint32_t sw128(uint32_t x) { return x ^ ((x >> 3) & 0x70); }

__device__ __forceinline__ void cpa16(uint32_t s, const void* g) {
    asm volatile("cp.async.cg.shared.global [%0], [%1], 16;" :: "r"(s), "l"(g));
}
__device__ __forceinline__ void cpa_commit() { asm volatile("cp.async.commit_group;" ::: "memory"); }
__device__ __forceinline__ void cpa_wait1()  { asm volatile("cp.async.wait_group 1;" ::: "memory"); }
__device__ __forceinline__ void cpa_wait0()  { asm volatile("cp.async.wait_group 0;" ::: "memory"); }

__device__ __forceinline__ void ldsm4(uint32_t r[4], uint32_t addr) {
    asm volatile("ldmatrix.sync.aligned.m8n8.x4.shared.b16 {%0,%1,%2,%3}, [%4];"
                 : "=r"(r[0]), "=r"(r[1]), "=r"(r[2]), "=r"(r[3]) : "r"(addr));
}
__device__ __forceinline__ void ldsm4t(uint32_t r[4], uint32_t addr) {
    asm volatile("ldmatrix.sync.aligned.m8n8.x4.trans.shared.b16 {%0,%1,%2,%3}, [%4];"
                 : "=r"(r[0]), "=r"(r[1]), "=r"(r[2]), "=r"(r[3]) : "r"(addr));
}

__device__ __forceinline__ void mma16816(float d[4], const uint32_t a[4], uint32_t b0, uint32_t b1) {
    asm volatile(
        "mma.sync.aligned.m16n8k16.row.col.f32.bf16.bf16.f32 "
        "{%0,%1,%2,%3}, {%4,%5,%6,%7}, {%8,%9}, {%0,%1,%2,%3};"
        : "+f"(d[0]), "+f"(d[1]), "+f"(d[2]), "+f"(d[3])
        : "r"(a[0]), "r"(a[1]), "r"(a[2]), "r"(a[3]), "r"(b0), "r"(b1));
}

__device__ __forceinline__ float ex2f(float x) {
    float y; asm("ex2.approx.ftz.f32 %0, %1;" : "=f"(y) : "f"(x)); return y;
}
__device__ __forceinline__ uint32_t packbf2(float lo, float hi) {
    __nv_bfloat162 h = __floats2bfloat162_rn(lo, hi);
    return *(uint32_t*)&h;
}

__device__ __forceinline__ uint32_t addrA(uint32_t base, int row0, int seg0, int lane) {
    int g = lane >> 3, i = lane & 7;
    int r = row0 + i + ((g & 1) << 3);
    int s = seg0 + (g >> 1);
    return base + sw128((uint32_t)(r * 128 + s * 16));
}
__device__ __forceinline__ uint32_t addrB(uint32_t base, int row0, int seg0, int lane) {
    int g = lane >> 3, i = lane & 7;
    int r = row0 + i + ((g >> 1) << 3);
    int s = seg0 + (g & 1);
    return base + sw128((uint32_t)(r * 128 + s * 16));
}

// ---------------- converts (merged, + chansum zero) ----------------
__global__ void convert_all(const float* __restrict__ feat,
                            const float* __restrict__ Wq, const float* __restrict__ Wk,
                            const float* __restrict__ Wv, const float* __restrict__ W1,
                            const float* __restrict__ W2, const float* __restrict__ W3) {
    int i = blockIdx.x * blockDim.x + threadIdx.x;
    if (i < BS * C_DIM) g_chansum[i] = 0.0f;
    const int tot2 = BS * C_DIM * NSEQ / 2;
    if (i < tot2) {
        float2 v = ((const float2*)feat)[i];
        ((__nv_bfloat162*)g_featbf)[i] = __floats2bfloat162_rn(v.x, v.y);
    }
    if (i < WTOT) {
        float v;
        if      (i < WOFF_K) v = Wq[i - WOFF_Q];
        else if (i < WOFF_V) v = Wk[i - WOFF_K];
        else if (i < WOFF_1) v = Wv[i - WOFF_V];
        else if (i < WOFF_2) v = W1[i - WOFF_1];
        else if (i < WOFF_3) v = W2[i - WOFF_2];
        else                 v = W3[i - WOFF_3];
        g_Wbf[i] = __float2bfloat16(v);
    }
}

// ---------------- qkv fused: single-barrier pipelines in both branches ----------------
__global__ __launch_bounds__(256, 2) void qkv_kernel(
    const __nv_bfloat16* __restrict__ Wqb, const __nv_bfloat16* __restrict__ Wkb,
    const __nv_bfloat16* __restrict__ Wvb, const __nv_bfloat16* __restrict__ X,
    const float* __restrict__ bq, const float* __restrict__ bk, const float* __restrict__ bv,
    __nv_bfloat16* __restrict__ outQ, __nv_bfloat16* __restrict__ outK,
    __nv_bfloat16* __restrict__ outV)
{
    extern __shared__ __align__(128) __nv_bfloat16 dyns[];
    const int tid = threadIdx.x, lane = tid & 31, w = tid >> 5;
    const int b = blockIdx.z;
    const __nv_bfloat16* Xb = X + (size_t)b * C_DIM * NSEQ;
    const uint32_t base = s2u(dyns);

    if (blockIdx.y < 4) {
        const int s0 = blockIdx.x * 128, ch0 = blockIdx.y * 64;

        auto load_stage = [&](int st, int k0) {
            const uint32_t Xa = base + st * 16384u;
            const uint32_t Qa = base + 32768u + st * 8192u;
            const uint32_t Ka = base + 49152u + st * 8192u;
            #pragma unroll
            for (int i = 0; i < 4; i++) {
                int e = tid + i * 256; int r = e >> 4, c = e & 15;
                int h = c >> 3, sg = c & 7;
                cpa16(Xa + h * 8192u + sw128((uint32_t)(r * 128 + sg * 16)),
                      Xb + (size_t)(k0 + r) * NSEQ + s0 + h * 64 + sg * 8);
            }
            #pragma unroll
            for (int i = 0; i < 2; i++) {
                int e = tid + i * 256; int r = e >> 3, sg = e & 7;
                cpa16(Qa + sw128((uint32_t)(r * 128 + sg * 16)), Wqb + (size_t)(ch0 + r) * 256 + k0 + sg * 8);
                cpa16(Ka + sw128((uint32_t)(r * 128 + sg * 16)), Wkb + (size_t)(ch0 + r) * 256 + k0 + sg * 8);
            }
        };

        load_stage(0, 0);
        cpa_commit();

        float qacc[8][4], kacc[8][4];
        #pragma unroll
        for (int j = 0; j < 8; j++)
            #pragma unroll
            for (int x = 0; x < 4; x++) { qacc[j][x] = 0.0f; kacc[j][x] = 0.0f; }

        for (int kt = 0; kt < 4; kt++) {
            cpa_wait0();
            __syncthreads();
            if (kt + 1 < 4) {
                load_stage((kt + 1) & 1, (kt + 1) * 64);
                cpa_commit();
            }

            const int st = kt & 1;
            const uint32_t Xh = base + st * 16384u + (w >> 2) * 8192u;
            const uint32_t Qa = base + 32768u + st * 8192u;
            const uint32_t Ka = base + 49152u + st * 8192u;

            uint32_t a[4][4];
            #pragma unroll
            for (int kk = 0; kk < 4; kk++)
                ldsm4t(a[kk], addrB(Xh, kk * 16, (w & 3) * 2, lane));

            #pragma unroll
            for (int j2 = 0; j2 < 4; j2++) {
                #pragma unroll
                for (int kk = 0; kk < 4; kk++) {
                    uint32_t bf[4];
                    ldsm4(bf, addrB(Qa, j2 * 16, kk * 2, lane));
                    mma16816(qacc[2 * j2],     a[kk], bf[0], bf[1]);
                    mma16816(qacc[2 * j2 + 1], a[kk], bf[2], bf[3]);
                }
                #pragma unroll
                for (int kk = 0; kk < 4; kk++) {
                    uint32_t bf[4];
                    ldsm4(bf, addrB(Ka, j2 * 16, kk * 2, lane));
                    mma16816(kacc[2 * j2],     a[kk], bf[0], bf[1]);
                    mma16816(kacc[2 * j2 + 1], a[kk], bf[2], bf[3]);
                }
            }
        }

        const int qA = s0 + w * 16 + (lane >> 2);
        const int qB = qA + 8;
        const size_t obo = ((size_t)(b * NH + blockIdx.y) * NSEQ) * 64;
        __nv_bfloat16* obQ = outQ + obo;
        __nv_bfloat16* obK = outK + obo;
        #pragma unroll
        for (int j = 0; j < 8; j++) {
            const int chl = j * 8 + (lane & 3) * 2;
            float2 bbq = *(const float2*)&bq[ch0 + chl];
            float2 bbk = *(const float2*)&bk[ch0 + chl];
            *(uint32_t*)&obQ[(size_t)qA * 64 + chl] = packbf2((qacc[j][0] + bbq.x) * C1F, (qacc[j][1] + bbq.y) * C1F);
            *(uint32_t*)&obQ[(size_t)qB * 64 + chl] = packbf2((qacc[j][2] + bbq.x) * C1F, (qacc[j][3] + bbq.y) * C1F);
            *(uint32_t*)&obK[(size_t)qA * 64 + chl] = packbf2(kacc[j][0] + bbk.x, kacc[j][1] + bbk.y);
            *(uint32_t*)&obK[(size_t)qB * 64 + chl] = packbf2(kacc[j][2] + bbk.x, kacc[j][3] + bbk.y);
        }
    } else {
        const int n0 = blockIdx.x * 128, m0 = (blockIdx.y - 4) * 64;
        const int mw = w & 3, nw = w >> 2;

        auto load_stage = [&](int st, int k0) {
            const uint32_t Aa = base + st * 24576u;
            const uint32_t Ba = Aa + 8192u;
            #pragma unroll
            for (int i = 0; i < 2; i++) {
                int e = tid + i * 256; int r = e >> 3, sg = e & 7;
                cpa16(Aa + sw128((uint32_t)(r * 128 + sg * 16)), Wvb + (size_t)(m0 + r) * 256 + k0 + sg * 8);
            }
            #pragma unroll
            for (int i = 0; i < 4; i++) {
                int e = tid + i * 256; int r = e >> 4, c = e & 15;
                int h = c >> 3, sg = c & 7;
                cpa16(Ba + h * 8192u + sw128((uint32_t)(r * 128 + sg * 16)),
                      Xb + (size_t)(k0 + r) * NSEQ + n0 + h * 64 + sg * 8);
            }
        };

        load_stage(0, 0);
        cpa_commit();

        float sacc[8][4];
        #pragma unroll
        for (int j = 0; j < 8; j++)
            #pragma unroll
            for (int x = 0; x < 4; x++) sacc[j][x] = 0.0f;

        for (int kt = 0; kt < 4; kt++) {
            cpa_wait0();
            __syncthreads();
            if (kt + 1 < 4) {
                load_stage((kt + 1) & 1, (kt + 1) * 64);
                cpa_commit();
            }

            const uint32_t Aa = base + (kt & 1) * 24576u;
            const uint32_t Bh = Aa + 8192u + nw * 8192u;

            uint32_t a[4][4];
            #pragma unroll
            for (int kk = 0; kk < 4; kk++)
                ldsm4(a[kk], addrA(Aa, mw * 16, kk * 2, lane));

            #pragma unroll
            for (int j2 = 0; j2 < 4; j2++) {
                #pragma unroll
                for (int kk = 0; kk < 4; kk++) {
                    uint32_t bf[4];
                    ldsm4t(bf, addrA(Bh, kk * 16, j2 * 2, lane));
                    mma16816(sacc[2 * j2],     a[kk], bf[0], bf[1]);
                    mma16816(sacc[2 * j2 + 1], a[kk], bf[2], bf[3]);
                }
            }
        }

        const int mA = m0 + mw * 16 + (lane >> 2);
        const int mB = mA + 8;
        const float biasA = bv[mA], biasB = bv[mB];
        __nv_bfloat16* ob = outV + (size_t)b * C_DIM * NSEQ;
        #pragma unroll
        for (int j = 0; j < 8; j++) {
            const int nl = n0 + nw * 64 + j * 8 + (lane & 3) * 2;
            *(uint32_t*)&ob[(size_t)mA * NSEQ + nl] = packbf2(sacc[j][0] + biasA, sacc[j][1] + biasA);
            *(uint32_t*)&ob[(size_t)mB * NSEQ + nl] = packbf2(sacc[j][2] + biasB, sacc[j][3] + biasB);
        }
    }
}

// ---------------- flash attention: 256 q/block, 512 thr, halved KV traffic ----------------
// dyn smem 96KB: Q 32K | stage0 {K 16K, V 16K} | stage1 {K 16K, V 16K}
__global__ __launch_bounds__(512, 1) void flash_mma(
    const __nv_bfloat16* __restrict__ Qt,
    const __nv_bfloat16* __restrict__ Kt,
    const __nv_bfloat16* __restrict__ Vc,
    const float* __restrict__ feat,
    __nv_bfloat16* __restrict__ xdiff)
{
    extern __shared__ __align__(128) __nv_bfloat16 fsm[];
    const uint32_t base = s2u(fsm);

    const int tid = threadIdx.x;
    const int lane = tid & 31;
    const int w = tid >> 5;              // 0..15, warp owns q rows w*16..w*16+15
    const int bh = blockIdx.y;
    const int q0 = blockIdx.x * 256;

    const uint32_t QSa = base;           // 256 rows x 128B = 32KB

    const __nv_bfloat16* Qg = Qt + (size_t)bh * NSEQ * 64;
    const __nv_bfloat16* Kg = Kt + (size_t)bh * NSEQ * 64;
    const __nv_bfloat16* Vg = Vc + (size_t)bh * 64 * NSEQ;

    auto load_kv = [&](int st, int k0) {
        const uint32_t KS = base + 32768u + (uint32_t)st * 32768u;
        const uint32_t VS = KS + 16384u;
        #pragma unroll
        for (int i = 0; i < 2; i++) {
            int e = tid + i * 512;
            int row = e >> 3, sg = e & 7;
            cpa16(KS + sw128((uint32_t)(row * 128 + sg * 16)), Kg + (size_t)(k0 + row) * 64 + sg * 8);
        }
        #pragma unroll
        for (int i = 0; i < 2; i++) {
            int e = tid + i * 512;
            int c = e >> 4, rem = e & 15;
            int p = rem >> 3, sg = rem & 7;
            cpa16(VS + p * 8192u + sw128((uint32_t)(c * 128 + sg * 16)),
                  Vg + (size_t)c * NSEQ + k0 + p * 64 + sg * 8);
        }
    };

    #pragma unroll
    for (int i = 0; i < 4; i++) {
        int e = tid + i * 512;
        int row = e >> 3, sg = e & 7;
        cpa16(QSa + sw128((uint32_t)(row * 128 + sg * 16)), Qg + (size_t)(q0 + row) * 64 + sg * 8);
    }
    load_kv(0, 0);
    cpa_commit();

    float l_lo = 0.0f, l_hi = 0.0f;
    float oacc[8][4];
    #pragma unroll
    for (int j = 0; j < 8; j++)
        #pragma unroll
        for (int x = 0; x < 4; x++) oacc[j][x] = 0.0f;
    uint32_t qa[4][4];

    for (int t = 0; t < 32; t++) {
        const int cur = t & 1;
        cpa_wait0();
        __syncthreads();

        if (t + 1 < 32) {
            load_kv(1 - cur, (t + 1) * 128);
            cpa_commit();
        }

        if (t == 0) {
            #pragma unroll
            for (int kk = 0; kk < 4; kk++)
                ldsm4(qa[kk], addrA(QSa, w * 16, kk * 2, lane));
        }

        const uint32_t KS = base + 32768u + (uint32_t)cur * 32768u;
        const uint32_t VS = KS + 16384u;

        #pragma unroll
        for (int j2 = 0; j2 < 8; j2++) {
            float s0a[4] = {0.0f, 0.0f, 0.0f, 0.0f};
            float s1a[4] = {0.0f, 0.0f, 0.0f, 0.0f};
            #pragma unroll
            for (int kk = 0; kk < 4; kk++) {
                uint32_t bq[4];
                ldsm4(bq, addrB(KS, j2 * 16, kk * 2, lane));
                mma16816(s0a, qa[kk], bq[0], bq[1]);
                mma16816(s1a, qa[kk], bq[2], bq[3]);
            }

            uint32_t a[4];
            {
                float p0 = ex2f(s0a[0]);
                float p1 = ex2f(s0a[1]);
                float p2 = ex2f(s0a[2]);
                float p3 = ex2f(s0a[3]);
                l_lo += p0 + p1; l_hi += p2 + p3;
                a[0] = packbf2(p0, p1);
                a[1] = packbf2(p2, p3);
                float p4 = ex2f(s1a[0]);
                float p5 = ex2f(s1a[1]);
                float p6 = ex2f(s1a[2]);
                float p7 = ex2f(s1a[3]);
                l_lo += p4 + p5; l_hi += p6 + p7;
                a[2] = packbf2(p4, p5);
                a[3] = packbf2(p6, p7);
            }

            const uint32_t Vp = VS + (uint32_t)(j2 >> 2) * 8192u;
            const int seg0 = (j2 & 3) * 2;
            #pragma unroll
            for (int cp = 0; cp < 4; cp++) {
                uint32_t bv4[4];
                ldsm4(bv4, addrB(Vp, cp * 16, seg0, lane));
                mma16816(oacc[2 * cp],     a, bv4[0], bv4[1]);
                mma16816(oacc[2 * cp + 1], a, bv4[2], bv4[3]);
            }
        }
    }

    l_lo += __shfl_xor_sync(0xffffffffu, l_lo, 1);
    l_lo += __shfl_xor_sync(0xffffffffu, l_lo, 2);
    l_hi += __shfl_xor_sync(0xffffffffu, l_hi, 1);
    l_hi += __shfl_xor_sync(0xffffffffu, l_hi, 2);
    const float inv_lo = 1.0f / l_lo;
    const float inv_hi = 1.0f / l_hi;

    // Ms staging: [64ch][264] bf16 = 33.8KB in the KV region (base + 32KB)
    __nv_bfloat16* Ms = fsm + 16384;
    const int qrl = w * 16 + (lane >> 2);
    #pragma unroll
    for (int ct = 0; ct < 8; ct++) {
        const int ch = ct * 8 + (lane & 3) * 2;
        Ms[ch * 264 + qrl]           = __float2bfloat16(oacc[ct][0] * inv_lo);
        Ms[(ch + 1) * 264 + qrl]     = __float2bfloat16(oacc[ct][1] * inv_lo);
        Ms[ch * 264 + qrl + 8]       = __float2bfloat16(oacc[ct][2] * inv_hi);
        Ms[(ch + 1) * 264 + qrl + 8] = __float2bfloat16(oacc[ct][3] * inv_hi);
    }
    __syncthreads();

    const float* fg = feat + (size_t)bh * 64 * NSEQ;
    __nv_bfloat16* xd = xdiff + (size_t)bh * 64 * NSEQ;
    #pragma unroll
    for (int i = 0; i < 16; i++) {
        int idx = tid + i * 512;               // 8192 float2 pairs
        int ch = idx >> 7, qp = (idx & 127) * 2;
        float2 f = *(const float2*)&fg[(size_t)ch * NSEQ + q0 + qp];
        float m0v = __bfloat162float(Ms[ch * 264 + qp]);
        float m1v = __bfloat162float(Ms[ch * 264 + qp + 1]);
        *(uint32_t*)&xd[(size_t)ch * NSEQ + q0 + qp] = packbf2(f.x - m0v, f.y - m1v);
    }
}

// ---------------- fused MLP (unchanged) ----------------
__device__ __forceinline__ void mlp_load_W(uint32_t dst, const __nv_bfloat16* W, int M, int K, int tid) {
    const int chunks = K >> 6;
    const int per_chunk = M * 8;
    const int total = chunks * per_chunk;
    for (int u = tid; u < total; u += 256) {
        int kc = u / per_chunk;
        int rem = u - kc * per_chunk;
        int m = rem >> 3, sg = rem & 7;
        cpa16(dst + (uint32_t)(kc * M * 128) + sw128((uint32_t)(m * 128 + sg * 16)),
              W + (size_t)m * K + kc * 64 + sg * 8);
    }
}

__global__ __launch_bounds__(256) void fused_mlp(
    const __nv_bfloat16* __restrict__ Wb,
    const __nv_bfloat16* __restrict__ xdiff,
    const float* __restrict__ b1, const float* __restrict__ g1, const float* __restrict__ be1,
    const float* __restrict__ m1, const float* __restrict__ v1,
    const float* __restrict__ b2, const float* __restrict__ g2, const float* __restrict__ be2,
    const float* __restrict__ m2, const float* __restrict__ v2,
    const float* __restrict__ b3,
    float* __restrict__ msg2)
{
    extern __shared__ __align__(128) __nv_bfloat16 dyns[];
    const int tid = threadIdx.x, lane = tid & 31, w = tid >> 5;
    const int s0 = blockIdx.x * 64, b = blockIdx.y;
    const uint32_t base = s2u(dyns);
    const uint32_t XD = base, H1 = base + 32768u, H2 = base + 49152u;
    const uint32_t WB0 = base + 65536u, WB1 = base + 131072u;

    const __nv_bfloat16* xd_g = xdiff + (size_t)b * C_DIM * NSEQ;

    for (int u = tid; u < 2048; u += 256) {
        int r = u >> 3, sg = u & 7;
        cpa16(XD + sw128((uint32_t)(r * 128 + sg * 16)), xd_g + (size_t)r * NSEQ + s0 + sg * 8);
    }
    mlp_load_W(WB0, Wb + WOFF_1, 128, 256, tid);
    cpa_commit();
    mlp_load_W(WB1, Wb + WOFF_2, 128, 128, tid);
    cpa_commit();

    cpa_wait1();
    __syncthreads();

    {
        float sacc[8][4];
        #pragma unroll
        for (int j = 0; j < 8; j++)
            #pragma unroll
            for (int x = 0; x < 4; x++) sacc[j][x] = 0.0f;

        for (int kc = 0; kc < 4; kc++) {
            const uint32_t Ac = WB0 + kc * 16384u;
            const uint32_t Bc = XD + kc * 8192u;
            uint32_t a[4][4];
            #pragma unroll
            for (int kk = 0; kk < 4; kk++)
                ldsm4(a[kk], addrA(Ac, w * 16, kk * 2, lane));
            #pragma unroll
            for (int j2 = 0; j2 < 4; j2++) {
                #pragma unroll
                for (int kk = 0; kk < 4; kk++) {
                    uint32_t bf[4];
                    ldsm4t(bf, addrA(Bc, kk * 16, j2 * 2, lane));
                    mma16816(sacc[2 * j2],     a[kk], bf[0], bf[1]);
                    mma16816(sacc[2 * j2 + 1], a[kk], bf[2], bf[3]);
                }
            }
        }

        const int mA = w * 16 + (lane >> 2);
        const int mB = mA + 8;
        float scA = g1[mA] * rsqrtf(v1[mA] + EPS), shA = be1[mA] - m1[mA] * scA;
        float scB = g1[mB] * rsqrtf(v1[mB] + EPS), shB = be1[mB] - m1[mB] * scB;
        const float bA = b1[mA], bB = b1[mB];
        #pragma unroll
        for (int j = 0; j < 8; j++) {
            const int nl = j * 8 + (lane & 3) * 2;
            float v0 = fmaxf((sacc[j][0] + bA) * scA + shA, 0.0f);
            float v1x = fmaxf((sacc[j][1] + bA) * scA + shA, 0.0f);
            float v2x = fmaxf((sacc[j][2] + bB) * scB + shB, 0.0f);
            float v3 = fmaxf((sacc[j][3] + bB) * scB + shB, 0.0f);
            *(uint32_t*)((char*)dyns + (H1 - base) + sw128((uint32_t)(mA * 128 + nl * 2))) = packbf2(v0, v1x);
            *(uint32_t*)((char*)dyns + (H1 - base) + sw128((uint32_t)(mB * 128 + nl * 2))) = packbf2(v2x, v3);
        }
    }
    __syncthreads();

    mlp_load_W(WB0, Wb + WOFF_3, 256, 128, tid);
    cpa_commit();

    cpa_wait1();
    __syncthreads();

    {
        float sacc[8][4];
        #pragma unroll
        for (int j = 0; j < 8; j++)
            #pragma unroll
            for (int x = 0; x < 4; x++) sacc[j][x] = 0.0f;

        for (int kc = 0; kc < 2; kc++) {
            const uint32_t Ac = WB1 + kc * 16384u;
            const uint32_t Bc = H1 + kc * 8192u;
            uint32_t a[4][4];
            #pragma unroll
            for (int kk = 0; kk < 4; kk++)
                ldsm4(a[kk], addrA(Ac, w * 16, kk * 2, lane));
            #pragma unroll
            for (int j2 = 0; j2 < 4; j2++) {
                #pragma unroll
                for (int kk = 0; kk < 4; kk++) {
                    uint32_t bf[4];
                    ldsm4t(bf, addrA(Bc, kk * 16, j2 * 2, lane));
                    mma16816(sacc[2 * j2],     a[kk], bf[0], bf[1]);
                    mma16816(sacc[2 * j2 + 1], a[kk], bf[2], bf[3]);
                }
            }
        }

        const int mA = w * 16 + (lane >> 2);
        const int mB = mA + 8;
        float scA = g2[mA] * rsqrtf(v2[mA] + EPS), shA = be2[mA] - m2[mA] * scA;
        float scB = g2[mB] * rsqrtf(v2[mB] + EPS), shB = be2[mB] - m2[mB] * scB;
        const float bA = b2[mA], bB = b2[mB];
        #pragma unroll
        for (int j = 0; j < 8; j++) {
            const int nl = j * 8 + (lane & 3) * 2;
            float v0 = fmaxf((sacc[j][0] + bA) * scA + shA, 0.0f);
            float v1x = fmaxf((sacc[j][1] + bA) * scA + shA, 0.0f);
            float v2x = fmaxf((sacc[j][2] + bB) * scB + shB, 0.0f);
            float v3 = fmaxf((sacc[j][3] + bB) * scB + shB, 0.0f);
            *(uint32_t*)((char*)dyns + (H2 - base) + sw128((uint32_t)(mA * 128 + nl * 2))) = packbf2(v0, v1x);
            *(uint32_t*)((char*)dyns + (H2 - base) + sw128((uint32_t)(mB * 128 + nl * 2))) = packbf2(v2x, v3);
        }
    }
    __syncthreads();

    cpa_wait0();
    __syncthreads();

    float* of = msg2 + (size_t)b * C_DIM * NSEQ;
    #pragma unroll
    for (int ms = 0; ms < 2; ms++) {
        float sacc[8][4];
        #pragma unroll
        for (int j = 0; j < 8; j++)
            #pragma unroll
            for (int x = 0; x < 4; x++) sacc[j][x] = 0.0f;

        const int mbase = ms * 128 + w * 16;
        for (int kc = 0; kc < 2; kc++) {
            const uint32_t Ac = WB0 + kc * 32768u;
            const uint32_t Bc = H2 + kc * 8192u;
            uint32_t a[4][4];
            #pragma unroll
            for (int kk = 0; kk < 4; kk++)
                ldsm4(a[kk], addrA(Ac, mbase, kk * 2, lane));
            #pragma unroll
            for (int j2 = 0; j2 < 4; j2++) {
                #pragma unroll
                for (int kk = 0; kk < 4; kk++) {
                    uint32_t bf[4];
                    ldsm4t(bf, addrA(Bc, kk * 16, j2 * 2, lane));
                    mma16816(sacc[2 * j2],     a[kk], bf[0], bf[1]);
                    mma16816(sacc[2 * j2 + 1], a[kk], bf[2], bf[3]);
                }
            }
        }

        const int mA = mbase + (lane >> 2);
        const int mB = mA + 8;
        const float bA = b3[mA], bB = b3[mB];
        float sA = 0.0f, sB = 0.0f;
        #pragma unroll
        for (int j = 0; j < 8; j++) {
            const int nl = s0 + j * 8 + (lane & 3) * 2;
            float v0 = sacc[j][0] + bA, v1x = sacc[j][1] + bA;
            float v2x = sacc[j][2] + bB, v3 = sacc[j][3] + bB;
            float2 f0 = {v0, v1x}, f1 = {v2x, v3};
            *(float2*)&of[(size_t)mA * NSEQ + nl] = f0;
            *(float2*)&of[(size_t)mB * NSEQ + nl] = f1;
            sA += v0 + v1x; sB += v2x + v3;
        }
        sA += __shfl_xor_sync(0xffffffffu, sA, 1);
        sA += __shfl_xor_sync(0xffffffffu, sA, 2);
        sB += __shfl_xor_sync(0xffffffffu, sB, 1);
        sB += __shfl_xor_sync(0xffffffffu, sB, 2);
        if ((lane & 3) == 0) {
            atomicAdd(&g_chansum[b * C_DIM + mA], sA);
            atomicAdd(&g_chansum[b * C_DIM + mB], sB);
        }
    }
}

// ---------------- SE gate (separate, confirmed best) ----------------
__global__ void se_kernel(const float* __restrict__ Wse1, const float* __restrict__ bse1,
                          const float* __restrict__ Wse2, const float* __restrict__ bse2)
{
    __shared__ float sq[BS * C_DIM];
    __shared__ float fc[BS * 16];
    const int tid = threadIdx.x;
    const float invn = 1.0f / (float)NSEQ;

    for (int e = tid; e < BS * C_DIM; e += blockDim.x)
        sq[e] = g_chansum[e] * invn;
    __syncthreads();

    if (tid < BS * 16) {
        int b = tid >> 4, r = tid & 15;
        float a = bse1[r];
        for (int c = 0; c < C_DIM; c++) a += sq[b * C_DIM + c] * Wse1[r * C_DIM + c];
        fc[b * 16 + r] = fmaxf(a, 0.0f);
    }
    __syncthreads();

    for (int e = tid; e < BS * C_DIM; e += blockDim.x) {
        int b = e >> 8, c = e & 255;
        float a = bse2[c];
        #pragma unroll
        for (int r = 0; r < 16; r++) a += fc[b * 16 + r] * Wse2[c * 16 + r];
        g_gate[e] = 1.0f / (1.0f + __expf(-a));
    }
}

// ---------------- final residual ----------------
__global__ void final_kernel(const float* __restrict__ feat, float* __restrict__ out)
{
    int i = blockIdx.x * blockDim.x + threadIdx.x;
    const int total4 = BS * C_DIM * NSEQ / 4;
    if (i >= total4) return;
    int ch = i >> 10;
    float gv = g_gate[ch];
    float4 f = ((const float4*)feat)[i];
    float4 m = ((const float4*)g_msg2)[i];
    float4 o;
    o.x = f.x + m.x * gv;
    o.y = f.y + m.y * gv;
    o.z = f.z + m.z * gv;
    o.w = f.w + m.w * gv;
    ((float4*)out)[i] = o;
}

// ---------------- launch ----------------
extern "C" void kernel_launch(void* const* d_in, const int* in_sizes, int n_in,
                              void* d_out, int out_size)
{
    const float* feat = (const float*)d_in[0];
    const float* Wq = (const float*)d_in[1];  const float* bq = (const float*)d_in[2];
    const float* Wk = (const float*)d_in[3];  const float* bk = (const float*)d_in[4];
    const float* Wv = (const float*)d_in[5];  const float* bv = (const float*)d_in[6];
    const float* W1 = (const float*)d_in[7];  const float* b1 = (const float*)d_in[8];
    const float* g1 = (const float*)d_in[9];  const float* be1 = (const float*)d_in[10];
    const float* m1 = (const float*)d_in[11]; const float* v1 = (const float*)d_in[12];
    const float* W2 = (const float*)d_in[13]; const float* b2 = (const float*)d_in[14];
    const float* g2 = (const float*)d_in[15]; const float* be2 = (const float*)d_in[16];
    const float* m2 = (const float*)d_in[17]; const float* v2 = (const float*)d_in[18];
    const float* W3 = (const float*)d_in[19]; const float* b3 = (const float*)d_in[20];
    const float* Wse1 = (const float*)d_in[21]; const float* bse1 = (const float*)d_in[22];
    const float* Wse2 = (const float*)d_in[23]; const float* bse2 = (const float*)d_in[24];

    __nv_bfloat16 *featbfp, *Wbfp, *Qtp, *Ktp, *Vcp, *xdp;
    float *msg2p;
    cudaGetSymbolAddress((void**)&featbfp, g_featbf);
    cudaGetSymbolAddress((void**)&Wbfp, g_Wbf);
    cudaGetSymbolAddress((void**)&Qtp, g_Qt);
    cudaGetSymbolAddress((void**)&Ktp, g_Kt);
    cudaGetSymbolAddress((void**)&Vcp, g_Vc);
    cudaGetSymbolAddress((void**)&xdp, g_xdiff);
    cudaGetSymbolAddress((void**)&msg2p, g_msg2);

    static bool attr_set = false;
    if (!attr_set) {
        cudaFuncSetAttribute(qkv_kernel, cudaFuncAttributeMaxDynamicSharedMemorySize, 65536);
        cudaFuncSetAttribute(flash_mma, cudaFuncAttributeMaxDynamicSharedMemorySize, 98304);
        cudaFuncSetAttribute(fused_mlp, cudaFuncAttributeMaxDynamicSharedMemorySize, 196608);
        attr_set = true;
    }

    convert_all<<<4096, 256>>>(feat, Wq, Wk, Wv, W1, W2, W3);

    qkv_kernel<<<dim3(32, 8, 2), 256, 65536>>>(Wbfp + WOFF_Q, Wbfp + WOFF_K, Wbfp + WOFF_V,
                                               featbfp, bq, bk, bv, Qtp, Ktp, Vcp);

    flash_mma<<<dim3(NSEQ / 256, BS * NH), 512, 98304>>>(Qtp, Ktp, Vcp, feat, xdp);

    fused_mlp<<<dim3(64, 2), 256, 196608>>>(Wbfp, xdp,
                                            b1, g1, be1, m1, v1,
                                            b2, g2, be2, m2, v2,
                                            b3, msg2p);

    se_kernel<<<1, 256>>>(Wse1, bse1, Wse2, bse2);

    const int total4 = BS * C_DIM * NSEQ / 4;
    final_kernel<<<(total4 + 255) / 256, 256>>>(feat, (float*)d_out);
}

// round 17
// speedup vs baseline: 1.1111x; 1.0137x over previous
#include <cuda_runtime.h>
#include <cuda_bf16.h>
#include <math.h>
#include <stdint.h>

#define C_DIM 256
#define CH_DIM 128
#define NSEQ 4096
#define BS 2
#define DH 64
#define NH 4
#define EPS 1e-5f
#define C1F 0.1803368801111204f   // 0.125 * log2(e)
#define ONESBF2 0x3F803F80u       // bf16x2 {1.0, 1.0}

// weight pack offsets (elements)
#define WOFF_Q 0
#define WOFF_K 65536
#define WOFF_V 131072
#define WOFF_1 196608
#define WOFF_2 229376
#define WOFF_3 245760
#define WTOT   278528

// ---------------- scratch ----------------
__device__ __align__(128) __nv_bfloat16 g_featbf[BS * C_DIM * NSEQ];
__device__ __align__(128) __nv_bfloat16 g_Wbf[WTOT];
__device__ __align__(128) __nv_bfloat16 g_Qt[BS * C_DIM * NSEQ];   // [bh][n][64] (pre-scaled by C1)
__device__ __align__(128) __nv_bfloat16 g_Kt[BS * C_DIM * NSEQ];   // [bh][n][64]
__device__ __align__(128) __nv_bfloat16 g_Vc[BS * C_DIM * NSEQ];   // [b][256][4096]
__device__ __align__(128) __nv_bfloat16 g_xdiff[BS * C_DIM * NSEQ];
__device__ float g_msg2[BS * C_DIM * NSEQ];
__device__ float g_chansum[BS * C_DIM];
__device__ float g_gate[BS * C_DIM];

// ---------------- PTX helpers ----------------
__device__ __forceinline__ uint32_t s2u(const void* p) {
    uint32_t a;
    asm("{ .reg .u64 t; cvta.to.shared.u64 t, %1; cvt.u32.u64 %0, t; }" : "=r"(a) : "l"(p));
    return a;
}
__device__ __forceinline__ uint32_t sw128(uint32_t x) { return x ^ ((x >> 3) & 0x70); }

__device__ __forceinline__ void cpa16(uint32_t s, const void* g) {
    asm volatile("cp.async.cg.shared.global [%0], [%1], 16;" :: "r"(s), "l"(g));
}
__device__ __forceinline__ void cpa_commit() { asm volatile("cp.async.commit_group;" ::: "memory"); }
__device__ __forceinline__ void cpa_wait0()  { asm volatile("cp.async.wait_group 0;" ::: "memory"); }
__device__ __forceinline__ void cpa_wait1()  { asm volatile("cp.async.wait_group 1;" ::: "memory"); }

__device__ __forceinline__ void ldsm4(uint32_t r[4], uint32_t addr) {
    asm volatile("ldmatrix.sync.aligned.m8n8.x4.shared.b16 {%0,%1,%2,%3}, [%4];"
                 : "=r"(r[0]), "=r"(r[1]), "=r"(r[2]), "=r"(r[3]) : "r"(addr));
}
__device__ __forceinline__ void ldsm4t(uint32_t r[4], uint32_t addr) {
    asm volatile("ldmatrix.sync.aligned.m8n8.x4.trans.shared.b16 {%0,%1,%2,%3}, [%4];"
                 : "=r"(r[0]), "=r"(r[1]), "=r"(r[2]), "=r"(r[3]) : "r"(addr));
}

__device__ __forceinline__ void mma16816(float d[4], const uint32_t a[4], uint32_t b0, uint32_t b1) {
    asm volatile(
        "mma.sync.aligned.m16n8k16.row.col.f32.bf16.bf16.f32 "
        "{%0,%1,%2,%3}, {%4,%5,%6,%7}, {%8,%9}, {%0,%1,%2,%3};"
        : "+f"(d[0]), "+f"(d[1]), "+f"(d[2]), "+f"(d[3])
        : "r"(a[0]), "r"(a[1]), "r"(a[2]), "r"(a[3]), "r"(b0), "r"(b1));
}

__device__ __forceinline__ float ex2f(float x) {
    float y; asm("ex2.approx.ftz.f32 %0, %1;" : "=f"(y) : "f"(x)); return y;
}
__device__ __forceinline__ uint32_t packbf2(float lo, float hi) {
    __nv_bfloat162 h = __floats2bfloat162_rn(lo, hi);
    return *(uint32_t*)&h;
}
// pack two fp32 into bf16x2: lo -> low half, hi -> high half
__device__ __forceinline__ uint32_t cvtbf2(float hi, float lo) {
    uint32_t d; asm("cvt.rn.bf16x2.f32 %0, %1, %2;" : "=r"(d) : "f"(hi), "f"(lo)); return d;
}
// elementwise 2^x on packed bf16x2 (one MUFU op for two elements)
__device__ __forceinline__ uint32_t ex2bf2(uint32_t x) {
    uint32_t y; asm("ex2.approx.ftz.bf16x2 %0, %1;" : "=r"(y) : "r"(x)); return y;
}

__device__ __forceinline__ uint32_t addrA(uint32_t base, int row0, int seg0, int lane) {
    int g = lane >> 3, i = lane & 7;
    int r = row0 + i + ((g & 1) << 3);
    int s = seg0 + (g >> 1);
    return base + sw128((uint32_t)(r * 128 + s * 16));
}
__device__ __forceinline__ uint32_t addrB(uint32_t base, int row0, int seg0, int lane) {
    int g = lane >> 3, i = lane & 7;
    int r = row0 + i + ((g >> 1) << 3);
    int s = seg0 + (g & 1);
    return base + sw128((uint32_t)(r * 128 + s * 16));
}

// ---------------- converts (merged, + chansum zero) ----------------
__global__ void convert_all(const float* __restrict__ feat,
                            const float* __restrict__ Wq, const float* __restrict__ Wk,
                            const float* __restrict__ Wv, const float* __restrict__ W1,
                            const float* __restrict__ W2, const float* __restrict__ W3) {
    int i = blockIdx.x * blockDim.x + threadIdx.x;
    if (i < BS * C_DIM) g_chansum[i] = 0.0f;
    const int tot2 = BS * C_DIM * NSEQ / 2;
    if (i < tot2) {
        float2 v = ((const float2*)feat)[i];
        ((__nv_bfloat162*)g_featbf)[i] = __floats2bfloat162_rn(v.x, v.y);
    }
    if (i < WTOT) {
        float v;
        if      (i < WOFF_K) v = Wq[i - WOFF_Q];
        else if (i < WOFF_V) v = Wk[i - WOFF_K];
        else if (i < WOFF_1) v = Wv[i - WOFF_V];
        else if (i < WOFF_2) v = W1[i - WOFF_1];
        else if (i < WOFF_3) v = W2[i - WOFF_2];
        else                 v = W3[i - WOFF_3];
        g_Wbf[i] = __float2bfloat16(v);
    }
}

// ---------------- qkv fused: single-barrier pipelines in both branches ----------------
__global__ __launch_bounds__(256, 2) void qkv_kernel(
    const __nv_bfloat16* __restrict__ Wqb, const __nv_bfloat16* __restrict__ Wkb,
    const __nv_bfloat16* __restrict__ Wvb, const __nv_bfloat16* __restrict__ X,
    const float* __restrict__ bq, const float* __restrict__ bk, const float* __restrict__ bv,
    __nv_bfloat16* __restrict__ outQ, __nv_bfloat16* __restrict__ outK,
    __nv_bfloat16* __restrict__ outV)
{
    extern __shared__ __align__(128) __nv_bfloat16 dyns[];
    const int tid = threadIdx.x, lane = tid & 31, w = tid >> 5;
    const int b = blockIdx.z;
    const __nv_bfloat16* Xb = X + (size_t)b * C_DIM * NSEQ;
    const uint32_t base = s2u(dyns);

    if (blockIdx.y < 4) {
        const int s0 = blockIdx.x * 128, ch0 = blockIdx.y * 64;

        auto load_stage = [&](int st, int k0) {
            const uint32_t Xa = base + st * 16384u;
            const uint32_t Qa = base + 32768u + st * 8192u;
            const uint32_t Ka = base + 49152u + st * 8192u;
            #pragma unroll
            for (int i = 0; i < 4; i++) {
                int e = tid + i * 256; int r = e >> 4, c = e & 15;
                int h = c >> 3, sg = c & 7;
                cpa16(Xa + h * 8192u + sw128((uint32_t)(r * 128 + sg * 16)),
                      Xb + (size_t)(k0 + r) * NSEQ + s0 + h * 64 + sg * 8);
            }
            #pragma unroll
            for (int i = 0; i < 2; i++) {
                int e = tid + i * 256; int r = e >> 3, sg = e & 7;
                cpa16(Qa + sw128((uint32_t)(r * 128 + sg * 16)), Wqb + (size_t)(ch0 + r) * 256 + k0 + sg * 8);
                cpa16(Ka + sw128((uint32_t)(r * 128 + sg * 16)), Wkb + (size_t)(ch0 + r) * 256 + k0 + sg * 8);
            }
        };

        load_stage(0, 0);
        cpa_commit();

        float qacc[8][4], kacc[8][4];
        #pragma unroll
        for (int j = 0; j < 8; j++)
            #pragma unroll
            for (int x = 0; x < 4; x++) { qacc[j][x] = 0.0f; kacc[j][x] = 0.0f; }

        for (int kt = 0; kt < 4; kt++) {
            cpa_wait0();
            __syncthreads();
            if (kt + 1 < 4) {
                load_stage((kt + 1) & 1, (kt + 1) * 64);
                cpa_commit();
            }

            const int st = kt & 1;
            const uint32_t Xh = base + st * 16384u + (w >> 2) * 8192u;
            const uint32_t Qa = base + 32768u + st * 8192u;
            const uint32_t Ka = base + 49152u + st * 8192u;

            uint32_t a[4][4];
            #pragma unroll
            for (int kk = 0; kk < 4; kk++)
                ldsm4t(a[kk], addrB(Xh, kk * 16, (w & 3) * 2, lane));

            #pragma unroll
            for (int j2 = 0; j2 < 4; j2++) {
                #pragma unroll
                for (int kk = 0; kk < 4; kk++) {
                    uint32_t bf[4];
                    ldsm4(bf, addrB(Qa, j2 * 16, kk * 2, lane));
                    mma16816(qacc[2 * j2],     a[kk], bf[0], bf[1]);
                    mma16816(qacc[2 * j2 + 1], a[kk], bf[2], bf[3]);
                }
                #pragma unroll
                for (int kk = 0; kk < 4; kk++) {
                    uint32_t bf[4];
                    ldsm4(bf, addrB(Ka, j2 * 16, kk * 2, lane));
                    mma16816(kacc[2 * j2],     a[kk], bf[0], bf[1]);
                    mma16816(kacc[2 * j2 + 1], a[kk], bf[2], bf[3]);
                }
            }
        }

        const int qA = s0 + w * 16 + (lane >> 2);
        const int qB = qA + 8;
        const size_t obo = ((size_t)(b * NH + blockIdx.y) * NSEQ) * 64;
        __nv_bfloat16* obQ = outQ + obo;
        __nv_bfloat16* obK = outK + obo;
        #pragma unroll
        for (int j = 0; j < 8; j++) {
            const int chl = j * 8 + (lane & 3) * 2;
            float2 bbq = *(const float2*)&bq[ch0 + chl];
            float2 bbk = *(const float2*)&bk[ch0 + chl];
            *(uint32_t*)&obQ[(size_t)qA * 64 + chl] = packbf2((qacc[j][0] + bbq.x) * C1F, (qacc[j][1] + bbq.y) * C1F);
            *(uint32_t*)&obQ[(size_t)qB * 64 + chl] = packbf2((qacc[j][2] + bbq.x) * C1F, (qacc[j][3] + bbq.y) * C1F);
            *(uint32_t*)&obK[(size_t)qA * 64 + chl] = packbf2(kacc[j][0] + bbk.x, kacc[j][1] + bbk.y);
            *(uint32_t*)&obK[(size_t)qB * 64 + chl] = packbf2(kacc[j][2] + bbk.x, kacc[j][3] + bbk.y);
        }
    } else {
        const int n0 = blockIdx.x * 128, m0 = (blockIdx.y - 4) * 64;
        const int mw = w & 3, nw = w >> 2;

        auto load_stage = [&](int st, int k0) {
            const uint32_t Aa = base + st * 24576u;
            const uint32_t Ba = Aa + 8192u;
            #pragma unroll
            for (int i = 0; i < 2; i++) {
                int e = tid + i * 256; int r = e >> 3, sg = e & 7;
                cpa16(Aa + sw128((uint32_t)(r * 128 + sg * 16)), Wvb + (size_t)(m0 + r) * 256 + k0 + sg * 8);
            }
            #pragma unroll
            for (int i = 0; i < 4; i++) {
                int e = tid + i * 256; int r = e >> 4, c = e & 15;
                int h = c >> 3, sg = c & 7;
                cpa16(Ba + h * 8192u + sw128((uint32_t)(r * 128 + sg * 16)),
                      Xb + (size_t)(k0 + r) * NSEQ + n0 + h * 64 + sg * 8);
            }
        };

        load_stage(0, 0);
        cpa_commit();

        float sacc[8][4];
        #pragma unroll
        for (int j = 0; j < 8; j++)
            #pragma unroll
            for (int x = 0; x < 4; x++) sacc[j][x] = 0.0f;

        for (int kt = 0; kt < 4; kt++) {
            cpa_wait0();
            __syncthreads();
            if (kt + 1 < 4) {
                load_stage((kt + 1) & 1, (kt + 1) * 64);
                cpa_commit();
            }

            const uint32_t Aa = base + (kt & 1) * 24576u;
            const uint32_t Bh = Aa + 8192u + nw * 8192u;

            uint32_t a[4][4];
            #pragma unroll
            for (int kk = 0; kk < 4; kk++)
                ldsm4(a[kk], addrA(Aa, mw * 16, kk * 2, lane));

            #pragma unroll
            for (int j2 = 0; j2 < 4; j2++) {
                #pragma unroll
                for (int kk = 0; kk < 4; kk++) {
                    uint32_t bf[4];
                    ldsm4t(bf, addrA(Bh, kk * 16, j2 * 2, lane));
                    mma16816(sacc[2 * j2],     a[kk], bf[0], bf[1]);
                    mma16816(sacc[2 * j2 + 1], a[kk], bf[2], bf[3]);
                }
            }
        }

        const int mA = m0 + mw * 16 + (lane >> 2);
        const int mB = mA + 8;
        const float biasA = bv[mA], biasB = bv[mB];
        __nv_bfloat16* ob = outV + (size_t)b * C_DIM * NSEQ;
        #pragma unroll
        for (int j = 0; j < 8; j++) {
            const int nl = n0 + nw * 64 + j * 8 + (lane & 3) * 2;
            *(uint32_t*)&ob[(size_t)mA * NSEQ + nl] = packbf2(sacc[j][0] + biasA, sacc[j][1] + biasA);
            *(uint32_t*)&ob[(size_t)mB * NSEQ + nl] = packbf2(sacc[j][2] + biasB, sacc[j][3] + biasB);
        }
    }
}

// ---------------- flash attention: 256 q/block, bf16x2 exp, l via MMA ----------------
// dyn smem 96KB: Q 32K | stage0 {K 16K, V 16K} | stage1 {K 16K, V 16K}
__global__ __launch_bounds__(512, 1) void flash_mma(
    const __nv_bfloat16* __restrict__ Qt,
    const __nv_bfloat16* __restrict__ Kt,
    const __nv_bfloat16* __restrict__ Vc,
    const float* __restrict__ feat,
    __nv_bfloat16* __restrict__ xdiff)
{
    extern __shared__ __align__(128) __nv_bfloat16 fsm[];
    const uint32_t base = s2u(fsm);

    const int tid = threadIdx.x;
    const int lane = tid & 31;
    const int w = tid >> 5;
    const int bh = blockIdx.y;
    const int q0 = blockIdx.x * 256;

    const uint32_t QSa = base;

    const __nv_bfloat16* Qg = Qt + (size_t)bh * NSEQ * 64;
    const __nv_bfloat16* Kg = Kt + (size_t)bh * NSEQ * 64;
    const __nv_bfloat16* Vg = Vc + (size_t)bh * 64 * NSEQ;

    auto load_kv = [&](int st, int k0) {
        const uint32_t KS = base + 32768u + (uint32_t)st * 32768u;
        const uint32_t VS = KS + 16384u;
        #pragma unroll
        for (int i = 0; i < 2; i++) {
            int e = tid + i * 512;
            int row = e >> 3, sg = e & 7;
            cpa16(KS + sw128((uint32_t)(row * 128 + sg * 16)), Kg + (size_t)(k0 + row) * 64 + sg * 8);
        }
        #pragma unroll
        for (int i = 0; i < 2; i++) {
            int e = tid + i * 512;
            int c = e >> 4, rem = e & 15;
            int p = rem >> 3, sg = rem & 7;
            cpa16(VS + p * 8192u + sw128((uint32_t)(c * 128 + sg * 16)),
                  Vg + (size_t)c * NSEQ + k0 + p * 64 + sg * 8);
        }
    };

    #pragma unroll
    for (int i = 0; i < 4; i++) {
        int e = tid + i * 512;
        int row = e >> 3, sg = e & 7;
        cpa16(QSa + sw128((uint32_t)(row * 128 + sg * 16)), Qg + (size_t)(q0 + row) * 64 + sg * 8);
    }
    load_kv(0, 0);
    cpa_commit();

    float lacc[4] = {0.0f, 0.0f, 0.0f, 0.0f};
    float oacc[8][4];
    #pragma unroll
    for (int j = 0; j < 8; j++)
        #pragma unroll
        for (int x = 0; x < 4; x++) oacc[j][x] = 0.0f;
    uint32_t qa[4][4];

    for (int t = 0; t < 32; t++) {
        const int cur = t & 1;
        cpa_wait0();
        __syncthreads();

        if (t + 1 < 32) {
            load_kv(1 - cur, (t + 1) * 128);
            cpa_commit();
        }

        if (t == 0) {
            #pragma unroll
            for (int kk = 0; kk < 4; kk++)
                ldsm4(qa[kk], addrA(QSa, w * 16, kk * 2, lane));
        }

        const uint32_t KS = base + 32768u + (uint32_t)cur * 32768u;
        const uint32_t VS = KS + 16384u;

        #pragma unroll
        for (int j2 = 0; j2 < 8; j2++) {
            float s0a[4] = {0.0f, 0.0f, 0.0f, 0.0f};
            float s1a[4] = {0.0f, 0.0f, 0.0f, 0.0f};
            #pragma unroll
            for (int kk = 0; kk < 4; kk++) {
                uint32_t bq[4];
                ldsm4(bq, addrB(KS, j2 * 16, kk * 2, lane));
                mma16816(s0a, qa[kk], bq[0], bq[1]);
                mma16816(s1a, qa[kk], bq[2], bq[3]);
            }

            // bf16x2 softmax: pack score pairs, one ex2 per pair; l via MMA below
            uint32_t a[4];
            a[0] = ex2bf2(cvtbf2(s0a[1], s0a[0]));
            a[1] = ex2bf2(cvtbf2(s0a[3], s0a[2]));
            a[2] = ex2bf2(cvtbf2(s1a[1], s1a[0]));
            a[3] = ex2bf2(cvtbf2(s1a[3], s1a[2]));

            // l += P @ ones (all 8 output cols identical row-sums; fp32 accum)
            mma16816(lacc, a, ONESBF2, ONESBF2);

            const uint32_t Vp = VS + (uint32_t)(j2 >> 2) * 8192u;
            const int seg0 = (j2 & 3) * 2;
            #pragma unroll
            for (int cp = 0; cp < 4; cp++) {
                uint32_t bv4[4];
                ldsm4(bv4, addrB(Vp, cp * 16, seg0, lane));
                mma16816(oacc[2 * cp],     a, bv4[0], bv4[1]);
                mma16816(oacc[2 * cp + 1], a, bv4[2], bv4[3]);
            }
        }
    }

    // every thread holds its full row sums: lacc[0] = row (lane>>2), lacc[2] = row+8
    const float inv_lo = 1.0f / lacc[0];
    const float inv_hi = 1.0f / lacc[2];

    __nv_bfloat16* Ms = fsm + 16384;
    const int qrl = w * 16 + (lane >> 2);
    #pragma unroll
    for (int ct = 0; ct < 8; ct++) {
        const int ch = ct * 8 + (lane & 3) * 2;
        Ms[ch * 264 + qrl]           = __float2bfloat16(oacc[ct][0] * inv_lo);
        Ms[(ch + 1) * 264 + qrl]     = __float2bfloat16(oacc[ct][1] * inv_lo);
        Ms[ch * 264 + qrl + 8]       = __float2bfloat16(oacc[ct][2] * inv_hi);
        Ms[(ch + 1) * 264 + qrl + 8] = __float2bfloat16(oacc[ct][3] * inv_hi);
    }
    __syncthreads();

    const float* fg = feat + (size_t)bh * 64 * NSEQ;
    __nv_bfloat16* xd = xdiff + (size_t)bh * 64 * NSEQ;
    #pragma unroll
    for (int i = 0; i < 16; i++) {
        int idx = tid + i * 512;
        int ch = idx >> 7, qp = (idx & 127) * 2;
        float2 f = *(const float2*)&fg[(size_t)ch * NSEQ + q0 + qp];
        float m0v = __bfloat162float(Ms[ch * 264 + qp]);
        float m1v = __bfloat162float(Ms[ch * 264 + qp + 1]);
        *(uint32_t*)&xd[(size_t)ch * NSEQ + q0 + qp] = packbf2(f.x - m0v, f.y - m1v);
    }
}

// ---------------- fused MLP (unchanged) ----------------
__device__ __forceinline__ void mlp_load_W(uint32_t dst, const __nv_bfloat16* W, int M, int K, int tid) {
    const int chunks = K >> 6;
    const int per_chunk = M * 8;
    const int total = chunks * per_chunk;
    for (int u = tid; u < total; u += 256) {
        int kc = u / per_chunk;
        int rem = u - kc * per_chunk;
        int m = rem >> 3, sg = rem & 7;
        cpa16(dst + (uint32_t)(kc * M * 128) + sw128((uint32_t)(m * 128 + sg * 16)),
              W + (size_t)m * K + kc * 64 + sg * 8);
    }
}

__global__ __launch_bounds__(256) void fused_mlp(
    const __nv_bfloat16* __restrict__ Wb,
    const __nv_bfloat16* __restrict__ xdiff,
    const float* __restrict__ b1, const float* __restrict__ g1, const float* __restrict__ be1,
    const float* __restrict__ m1, const float* __restrict__ v1,
    const float* __restrict__ b2, const float* __restrict__ g2, const float* __restrict__ be2,
    const float* __restrict__ m2, const float* __restrict__ v2,
    const float* __restrict__ b3,
    float* __restrict__ msg2)
{
    extern __shared__ __align__(128) __nv_bfloat16 dyns[];
    const int tid = threadIdx.x, lane = tid & 31, w = tid >> 5;
    const int s0 = blockIdx.x * 64, b = blockIdx.y;
    const uint32_t base = s2u(dyns);
    const uint32_t XD = base, H1 = base + 32768u, H2 = base + 49152u;
    const uint32_t WB0 = base + 65536u, WB1 = base + 131072u;

    const __nv_bfloat16* xd_g = xdiff + (size_t)b * C_DIM * NSEQ;

    for (int u = tid; u < 2048; u += 256) {
        int r = u >> 3, sg = u & 7;
        cpa16(XD + sw128((uint32_t)(r * 128 + sg * 16)), xd_g + (size_t)r * NSEQ + s0 + sg * 8);
    }
    mlp_load_W(WB0, Wb + WOFF_1, 128, 256, tid);
    cpa_commit();
    mlp_load_W(WB1, Wb + WOFF_2, 128, 128, tid);
    cpa_commit();

    cpa_wait1();
    __syncthreads();

    {
        float sacc[8][4];
        #pragma unroll
        for (int j = 0; j < 8; j++)
            #pragma unroll
            for (int x = 0; x < 4; x++) sacc[j][x] = 0.0f;

        for (int kc = 0; kc < 4; kc++) {
            const uint32_t Ac = WB0 + kc * 16384u;
            const uint32_t Bc = XD + kc * 8192u;
            uint32_t a[4][4];
            #pragma unroll
            for (int kk = 0; kk < 4; kk++)
                ldsm4(a[kk], addrA(Ac, w * 16, kk * 2, lane));
            #pragma unroll
            for (int j2 = 0; j2 < 4; j2++) {
                #pragma unroll
                for (int kk = 0; kk < 4; kk++) {
                    uint32_t bf[4];
                    ldsm4t(bf, addrA(Bc, kk * 16, j2 * 2, lane));
                    mma16816(sacc[2 * j2],     a[kk], bf[0], bf[1]);
                    mma16816(sacc[2 * j2 + 1], a[kk], bf[2], bf[3]);
                }
            }
        }

        const int mA = w * 16 + (lane >> 2);
        const int mB = mA + 8;
        float scA = g1[mA] * rsqrtf(v1[mA] + EPS), shA = be1[mA] - m1[mA] * scA;
        float scB = g1[mB] * rsqrtf(v1[mB] + EPS), shB = be1[mB] - m1[mB] * scB;
        const float bA = b1[mA], bB = b1[mB];
        #pragma unroll
        for (int j = 0; j < 8; j++) {
            const int nl = j * 8 + (lane & 3) * 2;
            float v0 = fmaxf((sacc[j][0] + bA) * scA + shA, 0.0f);
            float v1x = fmaxf((sacc[j][1] + bA) * scA + shA, 0.0f);
            float v2x = fmaxf((sacc[j][2] + bB) * scB + shB, 0.0f);
            float v3 = fmaxf((sacc[j][3] + bB) * scB + shB, 0.0f);
            *(uint32_t*)((char*)dyns + (H1 - base) + sw128((uint32_t)(mA * 128 + nl * 2))) = packbf2(v0, v1x);
            *(uint32_t*)((char*)dyns + (H1 - base) + sw128((uint32_t)(mB * 128 + nl * 2))) = packbf2(v2x, v3);
        }
    }
    __syncthreads();

    mlp_load_W(WB0, Wb + WOFF_3, 256, 128, tid);
    cpa_commit();

    cpa_wait1();
    __syncthreads();

    {
        float sacc[8][4];
        #pragma unroll
        for (int j = 0; j < 8; j++)
            #pragma unroll
            for (int x = 0; x < 4; x++) sacc[j][x] = 0.0f;

        for (int kc = 0; kc < 2; kc++) {
            const uint32_t Ac = WB1 + kc * 16384u;
            const uint32_t Bc = H1 + kc * 8192u;
            uint32_t a[4][4];
            #pragma unroll
            for (int kk = 0; kk < 4; kk++)
                ldsm4(a[kk], addrA(Ac, w * 16, kk * 2, lane));
            #pragma unroll
            for (int j2 = 0; j2 < 4; j2++) {
                #pragma unroll
                for (int kk = 0; kk < 4; kk++) {
                    uint32_t bf[4];
                    ldsm4t(bf, addrA(Bc, kk * 16, j2 * 2, lane));
                    mma16816(sacc[2 * j2],     a[kk], bf[0], bf[1]);
                    mma16816(sacc[2 * j2 + 1], a[kk], bf[2], bf[3]);
                }
            }
        }

        const int mA = w * 16 + (lane >> 2);
        const int mB = mA + 8;
        float scA = g2[mA] * rsqrtf(v2[mA] + EPS), shA = be2[mA] - m2[mA] * scA;
        float scB = g2[mB] * rsqrtf(v2[mB] + EPS), shB = be2[mB] - m2[mB] * scB;
        const float bA = b2[mA], bB = b2[mB];
        #pragma unroll
        for (int j = 0; j < 8; j++) {
            const int nl = j * 8 + (lane & 3) * 2;
            float v0 = fmaxf((sacc[j][0] + bA) * scA + shA, 0.0f);
            float v1x = fmaxf((sacc[j][1] + bA) * scA + shA, 0.0f);
            float v2x = fmaxf((sacc[j][2] + bB) * scB + shB, 0.0f);
            float v3 = fmaxf((sacc[j][3] + bB) * scB + shB, 0.0f);
            *(uint32_t*)((char*)dyns + (H2 - base) + sw128((uint32_t)(mA * 128 + nl * 2))) = packbf2(v0, v1x);
            *(uint32_t*)((char*)dyns + (H2 - base) + sw128((uint32_t)(mB * 128 + nl * 2))) = packbf2(v2x, v3);
        }
    }
    __syncthreads();

    cpa_wait0();
    __syncthreads();

    float* of = msg2 + (size_t)b * C_DIM * NSEQ;
    #pragma unroll
    for (int ms = 0; ms < 2; ms++) {
        float sacc[8][4];
        #pragma unroll
        for (int j = 0; j < 8; j++)
            #pragma unroll
            for (int x = 0; x < 4; x++) sacc[j][x] = 0.0f;

        const int mbase = ms * 128 + w * 16;
        for (int kc = 0; kc < 2; kc++) {
            const uint32_t Ac = WB0 + kc * 32768u;
            const uint32_t Bc = H2 + kc * 8192u;
            uint32_t a[4][4];
            #pragma unroll
            for (int kk = 0; kk < 4; kk++)
                ldsm4(a[kk], addrA(Ac, mbase, kk * 2, lane));
            #pragma unroll
            for (int j2 = 0; j2 < 4; j2++) {
                #pragma unroll
                for (int kk = 0; kk < 4; kk++) {
                    uint32_t bf[4];
                    ldsm4t(bf, addrA(Bc, kk * 16, j2 * 2, lane));
                    mma16816(sacc[2 * j2],     a[kk], bf[0], bf[1]);
                    mma16816(sacc[2 * j2 + 1], a[kk], bf[2], bf[3]);
                }
            }
        }

        const int mA = mbase + (lane >> 2);
        const int mB = mA + 8;
        const float bA = b3[mA], bB = b3[mB];
        float sA = 0.0f, sB = 0.0f;
        #pragma unroll
        for (int j = 0; j < 8; j++) {
            const int nl = s0 + j * 8 + (lane & 3) * 2;
            float v0 = sacc[j][0] + bA, v1x = sacc[j][1] + bA;
            float v2x = sacc[j][2] + bB, v3 = sacc[j][3] + bB;
            float2 f0 = {v0, v1x}, f1 = {v2x, v3};
            *(float2*)&of[(size_t)mA * NSEQ + nl] = f0;
            *(float2*)&of[(size_t)mB * NSEQ + nl] = f1;
            sA += v0 + v1x; sB += v2x + v3;
        }
        sA += __shfl_xor_sync(0xffffffffu, sA, 1);
        sA += __shfl_xor_sync(0xffffffffu, sA, 2);
        sB += __shfl_xor_sync(0xffffffffu, sB, 1);
        sB += __shfl_xor_sync(0xffffffffu, sB, 2);
        if ((lane & 3) == 0) {
            atomicAdd(&g_chansum[b * C_DIM + mA], sA);
            atomicAdd(&g_chansum[b * C_DIM + mB], sB);
        }
    }
}

// ---------------- SE gate (separate, confirmed best) ----------------
__global__ void se_kernel(const float* __restrict__ Wse1, const float* __restrict__ bse1,
                          const float* __restrict__ Wse2, const float* __restrict__ bse2)
{
    __shared__ float sq[BS * C_DIM];
    __shared__ float fc[BS * 16];
    const int tid = threadIdx.x;
    const float invn = 1.0f / (float)NSEQ;

    for (int e = tid; e < BS * C_DIM; e += blockDim.x)
        sq[e] = g_chansum[e] * invn;
    __syncthreads();

    if (tid < BS * 16) {
        int b = tid >> 4, r = tid & 15;
        float a = bse1[r];
        for (int c = 0; c < C_DIM; c++) a += sq[b * C_DIM + c] * Wse1[r * C_DIM + c];
        fc[b * 16 + r] = fmaxf(a, 0.0f);
    }
    __syncthreads();

    for (int e = tid; e < BS * C_DIM; e += blockDim.x) {
        int b = e >> 8, c = e & 255;
        float a = bse2[c];
        #pragma unroll
        for (int r = 0; r < 16; r++) a += fc[b * 16 + r] * Wse2[c * 16 + r];
        g_gate[e] = 1.0f / (1.0f + __expf(-a));
    }
}

// ---------------- final residual ----------------
__global__ void final_kernel(const float* __restrict__ feat, float* __restrict__ out)
{
    int i = blockIdx.x * blockDim.x + threadIdx.x;
    const int total4 = BS * C_DIM * NSEQ / 4;
    if (i >= total4) return;
    int ch = i >> 10;
    float gv = g_gate[ch];
    float4 f = ((const float4*)feat)[i];
    float4 m = ((const float4*)g_msg2)[i];
    float4 o;
    o.x = f.x + m.x * gv;
    o.y = f.y + m.y * gv;
    o.z = f.z + m.z * gv;
    o.w = f.w + m.w * gv;
    ((float4*)out)[i] = o;
}

// ---------------- launch ----------------
extern "C" void kernel_launch(void* const* d_in, const int* in_sizes, int n_in,
                              void* d_out, int out_size)
{
    const float* feat = (const float*)d_in[0];
    const float* Wq = (const float*)d_in[1];  const float* bq = (const float*)d_in[2];
    const float* Wk = (const float*)d_in[3];  const float* bk = (const float*)d_in[4];
    const float* Wv = (const float*)d_in[5];  const float* bv = (const float*)d_in[6];
    const float* W1 = (const float*)d_in[7];  const float* b1 = (const float*)d_in[8];
    const float* g1 = (const float*)d_in[9];  const float* be1 = (const float*)d_in[10];
    const float* m1 = (const float*)d_in[11]; const float* v1 = (const float*)d_in[12];
    const float* W2 = (const float*)d_in[13]; const float* b2 = (const float*)d_in[14];
    const float* g2 = (const float*)d_in[15]; const float* be2 = (const float*)d_in[16];
    const float* m2 = (const float*)d_in[17]; const float* v2 = (const float*)d_in[18];
    const float* W3 = (const float*)d_in[19]; const float* b3 = (const float*)d_in[20];
    const float* Wse1 = (const float*)d_in[21]; const float* bse1 = (const float*)d_in[22];
    const float* Wse2 = (const float*)d_in[23]; const float* bse2 = (const float*)d_in[24];

    __nv_bfloat16 *featbfp, *Wbfp, *Qtp, *Ktp, *Vcp, *xdp;
    float *msg2p;
    cudaGetSymbolAddress((void**)&featbfp, g_featbf);
    cudaGetSymbolAddress((void**)&Wbfp, g_Wbf);
    cudaGetSymbolAddress((void**)&Qtp, g_Qt);
    cudaGetSymbolAddress((void**)&Ktp, g_Kt);
    cudaGetSymbolAddress((void**)&Vcp, g_Vc);
    cudaGetSymbolAddress((void**)&xdp, g_xdiff);
    cudaGetSymbolAddress((void**)&msg2p, g_msg2);

    static bool attr_set = false;
    if (!attr_set) {
        cudaFuncSetAttribute(qkv_kernel, cudaFuncAttributeMaxDynamicSharedMemorySize, 65536);
        cudaFuncSetAttribute(flash_mma, cudaFuncAttributeMaxDynamicSharedMemorySize, 98304);
        cudaFuncSetAttribute(fused_mlp, cudaFuncAttributeMaxDynamicSharedMemorySize, 196608);
        attr_set = true;
    }

    convert_all<<<4096, 256>>>(feat, Wq, Wk, Wv, W1, W2, W3);

    qkv_kernel<<<dim3(32, 8, 2), 256, 65536>>>(Wbfp + WOFF_Q, Wbfp + WOFF_K, Wbfp + WOFF_V,
                                               featbfp, bq, bk, bv, Qtp, Ktp, Vcp);

    flash_mma<<<dim3(NSEQ / 256, BS * NH), 512, 98304>>>(Qtp, Ktp, Vcp, feat, xdp);

    fused_mlp<<<dim3(64, 2), 256, 196608>>>(Wbfp, xdp,
                                            b1, g1, be1, m1, v1,
                                            b2, g2, be2, m2, v2,
                                            b3, msg2p);

    se_kernel<<<1, 256>>>(Wse1, bse1, Wse2, bse2);

    const int total4 = BS * C_DIM * NSEQ / 4;
    final_kernel<<<(total4 + 255) / 256, 256>>>(feat, (float*)d_out);
}